// round 1
// baseline (speedup 1.0000x reference)
#include <cuda_runtime.h>
#include <math.h>

// Problem dims (fixed by reference)
#define B_ 64
#define D_ 512
#define M_ 1024
#define L_ 256
#define KK_ 30

// ---------------- scratch (device globals; no allocations allowed) ----------
__device__ float g_QWb[B_ * L_ * D_];   // Q @ W_b            [B,L,D]
__device__ float g_WvV[B_ * KK_ * M_];  // W_v @ V            [B,K,M]
__device__ float g_WqQ[B_ * KK_ * L_];  // W_q @ Q^T          [B,K,L]
__device__ float g_Yv [B_ * KK_ * D_];  // WqQ @ QWb          [B,K,D]
__device__ float g_Tv [B_ * KK_ * M_];  // Yv @ V             [B,K,M]
__device__ float g_Yq [B_ * KK_ * D_];  // WvV @ V^T          [B,K,D]
__device__ float g_Tq [B_ * KK_ * L_];  // Yq @ QWb^T         [B,K,L]
__device__ float g_zv [B_ * M_];        // logits / softmax v
__device__ float g_zq [B_ * L_];        // logits / softmax q
__device__ float g_v1 [B_ * D_];        // pooled v
__device__ float g_q1 [B_ * D_];        // pooled q

// ---------------- generic tiled GEMM: C = A(MxK) * B(KxN), row-major --------
template<int BM, int BN, int BK, int TM, int TN>
__global__ void gemm_nn_kernel(const float* __restrict__ A,
                               const float* __restrict__ Bm,
                               float* __restrict__ C,
                               int M, int N, int Kd,
                               int lda, int ldb, int ldc,
                               long sA, long sB, long sC)
{
    const int b = blockIdx.z;
    A  += (long)b * sA;
    Bm += (long)b * sB;
    C  += (long)b * sC;

    __shared__ float As[BK][BM + 1];   // +1 pad: conflict-free transposed store
    __shared__ float Bs[BK][BN];

    constexpr int TX = BN / TN;
    constexpr int TY = BM / TM;
    constexpr int NT = TX * TY;
    const int tid = threadIdx.x;
    const int tx = tid % TX;
    const int ty = tid / TX;

    const int row0 = blockIdx.y * BM;
    const int col0 = blockIdx.x * BN;

    float acc[TM][TN];
#pragma unroll
    for (int i = 0; i < TM; i++)
#pragma unroll
        for (int j = 0; j < TN; j++) acc[i][j] = 0.f;

    for (int k0 = 0; k0 < Kd; k0 += BK) {
        // Load A tile (BM x BK), coalesced over k within each row
#pragma unroll
        for (int idx = tid; idx < BM * BK; idx += NT) {
            int i  = idx / BK;
            int kk = idx % BK;
            int gr = row0 + i, gc = k0 + kk;
            As[kk][i] = (gr < M && gc < Kd) ? A[(long)gr * lda + gc] : 0.f;
        }
        // Load B tile (BK x BN), coalesced over n
#pragma unroll
        for (int idx = tid; idx < BK * BN; idx += NT) {
            int kk = idx / BN;
            int j  = idx % BN;
            int gr = k0 + kk, gc = col0 + j;
            Bs[kk][j] = (gr < Kd && gc < N) ? Bm[(long)gr * ldb + gc] : 0.f;
        }
        __syncthreads();

#pragma unroll
        for (int kk = 0; kk < BK; kk++) {
            float a[TM], bb[TN];
#pragma unroll
            for (int i = 0; i < TM; i++) a[i] = As[kk][ty * TM + i];
            // vectorized B read (BN row is 16B aligned, TN==4 path)
            if (TN == 4) {
                float4 v = *reinterpret_cast<const float4*>(&Bs[kk][tx * TN]);
                bb[0] = v.x; bb[1] = v.y; bb[2] = v.z; bb[3] = v.w;
            } else {
#pragma unroll
                for (int j = 0; j < TN; j++) bb[j] = Bs[kk][tx * TN + j];
            }
#pragma unroll
            for (int i = 0; i < TM; i++)
#pragma unroll
                for (int j = 0; j < TN; j++) acc[i][j] += a[i] * bb[j];
        }
        __syncthreads();
    }

#pragma unroll
    for (int i = 0; i < TM; i++) {
        int gr = row0 + ty * TM + i;
        if (gr >= M) continue;
#pragma unroll
        for (int j = 0; j < TN; j++) {
            int gc = col0 + tx * TN + j;
            if (gc < N) C[(long)gr * ldc + gc] = acc[i][j];
        }
    }
}

// ---------------- generic tiled GEMM NT: C = A(MxK) * B(NxK)^T --------------
template<int BM, int BN, int BK, int TM, int TN>
__global__ void gemm_nt_kernel(const float* __restrict__ A,
                               const float* __restrict__ Bm,
                               float* __restrict__ C,
                               int M, int N, int Kd,
                               int lda, int ldb, int ldc,
                               long sA, long sB, long sC)
{
    const int b = blockIdx.z;
    A  += (long)b * sA;
    Bm += (long)b * sB;
    C  += (long)b * sC;

    __shared__ float As[BK][BM + 1];
    __shared__ float Bs[BK][BN + 1];

    constexpr int TX = BN / TN;
    constexpr int TY = BM / TM;
    constexpr int NT = TX * TY;
    const int tid = threadIdx.x;
    const int tx = tid % TX;
    const int ty = tid / TX;

    const int row0 = blockIdx.y * BM;
    const int col0 = blockIdx.x * BN;

    float acc[TM][TN];
#pragma unroll
    for (int i = 0; i < TM; i++)
#pragma unroll
        for (int j = 0; j < TN; j++) acc[i][j] = 0.f;

    for (int k0 = 0; k0 < Kd; k0 += BK) {
#pragma unroll
        for (int idx = tid; idx < BM * BK; idx += NT) {
            int i  = idx / BK;
            int kk = idx % BK;
            int gr = row0 + i, gc = k0 + kk;
            As[kk][i] = (gr < M && gc < Kd) ? A[(long)gr * lda + gc] : 0.f;
        }
#pragma unroll
        for (int idx = tid; idx < BN * BK; idx += NT) {
            int j  = idx / BK;
            int kk = idx % BK;
            int gr = col0 + j, gc = k0 + kk;
            Bs[kk][j] = (gr < N && gc < Kd) ? Bm[(long)gr * ldb + gc] : 0.f;
        }
        __syncthreads();

#pragma unroll
        for (int kk = 0; kk < BK; kk++) {
            float a[TM], bb[TN];
#pragma unroll
            for (int i = 0; i < TM; i++) a[i] = As[kk][ty * TM + i];
#pragma unroll
            for (int j = 0; j < TN; j++) bb[j] = Bs[kk][tx * TN + j];
#pragma unroll
            for (int i = 0; i < TM; i++)
#pragma unroll
                for (int j = 0; j < TN; j++) acc[i][j] += a[i] * bb[j];
        }
        __syncthreads();
    }

#pragma unroll
    for (int i = 0; i < TM; i++) {
        int gr = row0 + ty * TM + i;
        if (gr >= M) continue;
#pragma unroll
        for (int j = 0; j < TN; j++) {
            int gc = col0 + tx * TN + j;
            if (gc < N) C[(long)gr * ldc + gc] = acc[i][j];
        }
    }
}

// ---------------- logits: z[b,m] = sum_k w[k] * tanh(X1[b,k,m] + X2[b,k,m]) -
__global__ void logits_kernel(const float* __restrict__ X1,
                              const float* __restrict__ X2,
                              const float* __restrict__ w,
                              float* __restrict__ z, int n)
{
    int idx = blockIdx.x * blockDim.x + threadIdx.x;
    if (idx >= B_ * n) return;
    int b = idx / n;
    int m = idx - b * n;
    const float* p1 = X1 + (long)b * KK_ * n + m;
    const float* p2 = X2 + (long)b * KK_ * n + m;
    float acc = 0.f;
#pragma unroll
    for (int k = 0; k < KK_; k++)
        acc += w[k] * tanhf(p1[(long)k * n] + p2[(long)k * n]);
    z[idx] = acc;
}

// ---------------- row softmax, in place -------------------------------------
__global__ void softmax_kernel(float* __restrict__ z, int n)
{
    const int b = blockIdx.x;
    float* row = z + (long)b * n;
    __shared__ float red[256];
    const int tid = threadIdx.x;

    float mx = -1e30f;
    for (int i = tid; i < n; i += 256) mx = fmaxf(mx, row[i]);
    red[tid] = mx; __syncthreads();
    for (int s = 128; s > 0; s >>= 1) {
        if (tid < s) red[tid] = fmaxf(red[tid], red[tid + s]);
        __syncthreads();
    }
    mx = red[0]; __syncthreads();

    float sum = 0.f;
    for (int i = tid; i < n; i += 256) {
        float e = expf(row[i] - mx);
        row[i] = e;
        sum += e;
    }
    red[tid] = sum; __syncthreads();
    for (int s = 128; s > 0; s >>= 1) {
        if (tid < s) red[tid] += red[tid + s];
        __syncthreads();
    }
    float inv = 1.f / red[0];
    for (int i = tid; i < n; i += 256) row[i] *= inv;
}

// ---------------- pooled v: v1[b,d] = sum_m a[b,m] * V[b,d,m] ----------------
__global__ void pool_v_kernel(const float* __restrict__ V,
                              const float* __restrict__ a,
                              float* __restrict__ v1)
{
    const int b = blockIdx.y;
    const int warp = threadIdx.x >> 5;
    const int lane = threadIdx.x & 31;
    const int d = blockIdx.x * 8 + warp;
    const float* vr = V + ((long)b * D_ + d) * M_;
    const float* ar = a + (long)b * M_;
    float acc = 0.f;
    for (int m = lane; m < M_; m += 32) acc += ar[m] * vr[m];
#pragma unroll
    for (int o = 16; o > 0; o >>= 1) acc += __shfl_down_sync(0xffffffffu, acc, o);
    if (lane == 0) v1[b * D_ + d] = acc;
}

// ---------------- pooled q: q1[b,d] = sum_l a[b,l] * Q[b,l,d] ----------------
__global__ void pool_q_kernel(const float* __restrict__ Q,
                              const float* __restrict__ a,
                              float* __restrict__ q1)
{
    const int b = blockIdx.x;
    __shared__ float as[L_];
    for (int i = threadIdx.x; i < L_; i += blockDim.x) as[i] = a[b * L_ + i];
    __syncthreads();
    const int d = threadIdx.x;  // blockDim = 512
    const float* qb = Q + (long)b * L_ * D_;
    float acc = 0.f;
#pragma unroll 8
    for (int l = 0; l < L_; l++) acc += as[l] * qb[(long)l * D_ + d];
    q1[b * D_ + d] = acc;
}

// ---------------- broadcast writer: out[b, r, :] = src[b, :] ----------------
__global__ void bcast_kernel(float4* __restrict__ out,
                             const float4* __restrict__ src,
                             int rows)
{
    const long total4 = (long)B_ * rows * (D_ / 4);
    long i = (long)blockIdx.x * blockDim.x + threadIdx.x;
    if (i >= total4) return;
    int d4 = (int)(i % (D_ / 4));
    long br = i / (D_ / 4);
    int b = (int)(br / rows);
    out[i] = __ldg(&src[(long)b * (D_ / 4) + d4]);
}

// ---------------- launch ----------------------------------------------------
extern "C" void kernel_launch(void* const* d_in, const int* in_sizes, int n_in,
                              void* d_out, int out_size)
{
    const float* V   = (const float*)d_in[0];  // [B, D, M]
    const float* Q   = (const float*)d_in[1];  // [B, L, D]
    const float* W_b = (const float*)d_in[2];  // [D, D]
    const float* W_v = (const float*)d_in[3];  // [K, D]
    const float* W_q = (const float*)d_in[4];  // [K, D]
    const float* whv = (const float*)d_in[5];  // [K]
    const float* whq = (const float*)d_in[6];  // [K]
    float* out = (float*)d_out;

    float *p_QWb, *p_WvV, *p_WqQ, *p_Yv, *p_Tv, *p_Yq, *p_Tq;
    float *p_zv, *p_zq, *p_v1, *p_q1;
    cudaGetSymbolAddress((void**)&p_QWb, g_QWb);
    cudaGetSymbolAddress((void**)&p_WvV, g_WvV);
    cudaGetSymbolAddress((void**)&p_WqQ, g_WqQ);
    cudaGetSymbolAddress((void**)&p_Yv,  g_Yv);
    cudaGetSymbolAddress((void**)&p_Tv,  g_Tv);
    cudaGetSymbolAddress((void**)&p_Yq,  g_Yq);
    cudaGetSymbolAddress((void**)&p_Tq,  g_Tq);
    cudaGetSymbolAddress((void**)&p_zv,  g_zv);
    cudaGetSymbolAddress((void**)&p_zq,  g_zq);
    cudaGetSymbolAddress((void**)&p_v1,  g_v1);
    cudaGetSymbolAddress((void**)&p_q1,  g_q1);

    // 1) QWb[b,l,e] = sum_d Q[b,l,d] W_b[d,e]      (dense: 16384x512x512)
    {
        dim3 grid(D_ / 64, (B_ * L_) / 64, 1);
        gemm_nn_kernel<64, 64, 32, 4, 4><<<grid, 256>>>(
            Q, W_b, p_QWb, B_ * L_, D_, D_, D_, D_, D_, 0, 0, 0);
    }
    // 2) WvV[b,k,m] = sum_d W_v[k,d] V[b,d,m]      (30x1024x512, batched)
    {
        dim3 grid(M_ / 64, 1, B_);
        gemm_nn_kernel<32, 64, 32, 2, 4><<<grid, 256>>>(
            W_v, V, p_WvV, KK_, M_, D_, D_, M_, M_,
            0, (long)D_ * M_, (long)KK_ * M_);
    }
    // 3) WqQ[b,k,l] = sum_d W_q[k,d] Q[b,l,d]      (NT: 30x256x512, batched)
    {
        dim3 grid(L_ / 64, 1, B_);
        gemm_nt_kernel<32, 64, 32, 2, 4><<<grid, 256>>>(
            W_q, Q, p_WqQ, KK_, L_, D_, D_, D_, L_,
            0, (long)L_ * D_, (long)KK_ * L_);
    }
    // 4) Yv[b,k,e] = sum_l WqQ[b,k,l] QWb[b,l,e]   (30x512x256, batched)
    {
        dim3 grid(D_ / 64, 1, B_);
        gemm_nn_kernel<32, 64, 32, 2, 4><<<grid, 256>>>(
            p_WqQ, p_QWb, p_Yv, KK_, D_, L_, L_, D_, D_,
            (long)KK_ * L_, (long)L_ * D_, (long)KK_ * D_);
    }
    // 5) Tv[b,k,m] = sum_e Yv[b,k,e] V[b,e,m]      (30x1024x512, batched)
    {
        dim3 grid(M_ / 64, 1, B_);
        gemm_nn_kernel<32, 64, 32, 2, 4><<<grid, 256>>>(
            p_Yv, V, p_Tv, KK_, M_, D_, D_, M_, M_,
            (long)KK_ * D_, (long)D_ * M_, (long)KK_ * M_);
    }
    // 6) Yq[b,k,e] = sum_m WvV[b,k,m] V[b,e,m]     (NT: 30x512x1024, batched)
    {
        dim3 grid(D_ / 64, 1, B_);
        gemm_nt_kernel<32, 64, 32, 2, 4><<<grid, 256>>>(
            p_WvV, V, p_Yq, KK_, D_, M_, M_, M_, D_,
            (long)KK_ * M_, (long)D_ * M_, (long)KK_ * D_);
    }
    // 7) Tq[b,k,l] = sum_e Yq[b,k,e] QWb[b,l,e]    (NT: 30x256x512, batched)
    {
        dim3 grid(L_ / 64, 1, B_);
        gemm_nt_kernel<32, 64, 32, 2, 4><<<grid, 256>>>(
            p_Yq, p_QWb, p_Tq, KK_, L_, D_, D_, D_, L_,
            (long)KK_ * D_, (long)L_ * D_, (long)KK_ * L_);
    }

    // 8) logits + softmax
    logits_kernel<<<(B_ * M_ + 255) / 256, 256>>>(p_WvV, p_Tv, whv, p_zv, M_);
    logits_kernel<<<(B_ * L_ + 255) / 256, 256>>>(p_WqQ, p_Tq, whq, p_zq, L_);
    softmax_kernel<<<B_, 256>>>(p_zv, M_);
    softmax_kernel<<<B_, 256>>>(p_zq, L_);

    // 9) pooled vectors
    {
        dim3 grid(D_ / 8, B_);
        pool_v_kernel<<<grid, 256>>>(V, p_zv, p_v1);
    }
    pool_q_kernel<<<B_, 512>>>(Q, p_zq, p_q1);

    // 10) broadcast to outputs: v [B,M,D] then q [B,L,D]
    {
        long n4v = (long)B_ * M_ * (D_ / 4);
        bcast_kernel<<<(unsigned)((n4v + 255) / 256), 256>>>(
            (float4*)out, (const float4*)p_v1, M_);
        long n4q = (long)B_ * L_ * (D_ / 4);
        float* out_q = out + (long)B_ * M_ * D_;
        bcast_kernel<<<(unsigned)((n4q + 255) / 256), 256>>>(
            (float4*)out_q, (const float4*)p_q1, L_);
    }
}

// round 2
// speedup vs baseline: 2.4189x; 2.4189x over previous
#include <cuda_runtime.h>
#include <math.h>
#include <stdint.h>

// Problem dims (fixed by reference)
#define B_ 64
#define D_ 512
#define M_ 1024
#define L_ 256
#define KK_ 30

// ---------------- scratch (device globals; no allocations allowed) ----------
__device__ float g_WqQ[B_ * KK_ * L_];  // W_q @ Q^T          [B,K,L]
__device__ float g_P  [B_ * KK_ * D_];  // WqQ @ Q            [B,K,D]
__device__ float g_Yv [B_ * KK_ * D_];  // P @ W_b            [B,K,D]
__device__ float g_WvV[B_ * KK_ * M_];  // W_v @ V            [B,K,M]
__device__ float g_Yq [B_ * KK_ * D_];  // WvV @ V^T          [B,K,D]
__device__ float g_R  [B_ * KK_ * D_];  // Yq @ W_b^T         [B,K,D]
__device__ float g_zv [B_ * M_];        // logits / softmax v
__device__ float g_zq [B_ * L_];        // logits / softmax q
__device__ float g_v1 [B_ * D_];        // pooled v
__device__ float g_q1 [B_ * D_];        // pooled q

// ---------------- async-copy helpers ----------------------------------------
__device__ __forceinline__ uint32_t s2u(const void* p) {
    return (uint32_t)__cvta_generic_to_shared(p);
}
__device__ __forceinline__ void cp16(uint32_t dst, const void* src, int sz) {
    asm volatile("cp.async.cg.shared.global [%0], [%1], 16, %2;"
                 :: "r"(dst), "l"(src), "r"(sz));
}
__device__ __forceinline__ void cp_commit() {
    asm volatile("cp.async.commit_group;");
}
__device__ __forceinline__ void cp_wait0() {
    asm volatile("cp.async.wait_group 0;");
}

// ---------------- skinny GEMM: C[30,N] = A[30,Kd] @ B ------------------------
// NN:  B stored [Kd][N]   (ldb = row stride)
// TB:  B stored [N][Kd]   (ldb = row stride) -> transposed through regs+STS
// FUSE: instead of writing C, compute z[col] = sum_k w[k]*tanh(acc + X[k,col])
#define BKx 32
#define BNx 128
#define ASTR 36    // As row stride (floats), 144B (16B multiple)
#define BSTR 132   // Bs row stride (floats), 528B (16B multiple)

template<bool TRANS_B, bool FUSE>
__global__ void __launch_bounds__(128)
skinny_gemm(const float* __restrict__ A, const float* __restrict__ Bm,
            float* __restrict__ C, int N, int Kd, int ldb,
            long sA, long sB, long sC,
            const float* __restrict__ X, const float* __restrict__ wv,
            float* __restrict__ z)
{
    __shared__ __align__(16) float As[2][32][ASTR];
    __shared__ __align__(16) float Bs[2][BKx][BSTR];
    __shared__ float zred[8][BNx];

    const int b    = blockIdx.y;
    const int col0 = blockIdx.x * BNx;
    const float* Ab = A  + (long)b * sA;
    const float* Bb = Bm + (long)b * sB;

    const int tid = threadIdx.x;
    const int tx = tid & 15;      // col group (8 cols)
    const int ty = tid >> 4;      // row group (4 rows)

    // A staging: thread -> row ar, k-offset ac (8 floats = 2 x 16B)
    const int ar = tid >> 2;
    const int ac = (tid & 3) * 8;
    const float* aSrc = Ab + (long)(ar < KK_ ? ar : 0) * Kd + ac;
    const int aSz = (ar < KK_) ? 16 : 0;

    // B NN staging: thread -> kk row, 32-col chunk (8 x 16B)
    const int bkk = tid >> 2;
    const int bcc = (tid & 3) * 32;
    const float* bNN = Bb + (long)bkk * ldb + col0 + bcc;

    // B TRANS staging: thread -> output-col row (col0+tid), 32 k's (8 float4)
    const float* bT = Bb + (long)(col0 + tid) * ldb;

    float4 bt[8];
    const int T = Kd / BKx;

    // ---- prologue: stage tile 0 into buf 0
    {
        uint32_t da = s2u(&As[0][ar][ac]);
        cp16(da,      aSrc,     aSz);
        cp16(da + 16, aSrc + 4, aSz);
        if (!TRANS_B) {
            uint32_t db = s2u(&Bs[0][bkk][bcc]);
#pragma unroll
            for (int i = 0; i < 8; i++) cp16(db + i * 16, bNN + i * 4, 16);
        } else {
#pragma unroll
            for (int i = 0; i < 8; i++)
                bt[i] = *reinterpret_cast<const float4*>(bT + i * 4);
        }
        cp_commit();
    }

    float acc[4][8];
#pragma unroll
    for (int i = 0; i < 4; i++)
#pragma unroll
        for (int j = 0; j < 8; j++) acc[i][j] = 0.f;

    for (int t = 0; t < T; t++) {
        const int buf = t & 1;
        cp_wait0();
        __syncthreads();   // tile t visible; all threads done with buf^1

        if (TRANS_B) {
            // store regs (tile t) into Bs[buf]; conflict-free (consecutive cols)
#pragma unroll
            for (int i = 0; i < 8; i++) {
                Bs[buf][i * 4 + 0][tid] = bt[i].x;
                Bs[buf][i * 4 + 1][tid] = bt[i].y;
                Bs[buf][i * 4 + 2][tid] = bt[i].z;
                Bs[buf][i * 4 + 3][tid] = bt[i].w;
            }
        }

        if (t + 1 < T) {
            const int nb = buf ^ 1;
            const float* ap = aSrc + (t + 1) * BKx;
            uint32_t da = s2u(&As[nb][ar][ac]);
            cp16(da,      ap,     aSz);
            cp16(da + 16, ap + 4, aSz);
            if (!TRANS_B) {
                const float* bp = bNN + (long)(t + 1) * BKx * ldb;
                uint32_t db = s2u(&Bs[nb][bkk][bcc]);
#pragma unroll
                for (int i = 0; i < 8; i++) cp16(db + i * 16, bp + i * 4, 16);
            }
            cp_commit();
            if (TRANS_B) {
                const float* bp = bT + (t + 1) * BKx;
#pragma unroll
                for (int i = 0; i < 8; i++)
                    bt[i] = *reinterpret_cast<const float4*>(bp + i * 4);
            }
        }

        if (TRANS_B) __syncthreads();   // make STS'd tile visible to all

        // ---- compute tile t
#pragma unroll
        for (int kk = 0; kk < BKx; kk++) {
            float av[4];
#pragma unroll
            for (int i = 0; i < 4; i++) av[i] = As[buf][ty * 4 + i][kk];
            float4 b0 = *reinterpret_cast<const float4*>(&Bs[buf][kk][tx * 8]);
            float4 b1 = *reinterpret_cast<const float4*>(&Bs[buf][kk][tx * 8 + 4]);
            float bv[8] = {b0.x, b0.y, b0.z, b0.w, b1.x, b1.y, b1.z, b1.w};
#pragma unroll
            for (int i = 0; i < 4; i++)
#pragma unroll
                for (int j = 0; j < 8; j++) acc[i][j] += av[i] * bv[j];
        }
    }

    if (!FUSE) {
#pragma unroll
        for (int i = 0; i < 4; i++) {
            int r = ty * 4 + i;
            if (r < KK_) {
                float* cp_ = C + (long)b * sC + (long)r * N + col0 + tx * 8;
                float4 o0 = make_float4(acc[i][0], acc[i][1], acc[i][2], acc[i][3]);
                float4 o1 = make_float4(acc[i][4], acc[i][5], acc[i][6], acc[i][7]);
                *reinterpret_cast<float4*>(cp_)     = o0;
                *reinterpret_cast<float4*>(cp_ + 4) = o1;
            }
        }
    } else {
        float part[8];
#pragma unroll
        for (int j = 0; j < 8; j++) part[j] = 0.f;
#pragma unroll
        for (int i = 0; i < 4; i++) {
            int r = ty * 4 + i;
            if (r < KK_) {
                const float* xp = X + (long)b * (long)KK_ * N + (long)r * N
                                    + col0 + tx * 8;
                float w = __ldg(&wv[r]);
                float4 x0 = *reinterpret_cast<const float4*>(xp);
                float4 x1 = *reinterpret_cast<const float4*>(xp + 4);
                float xv[8] = {x0.x, x0.y, x0.z, x0.w, x1.x, x1.y, x1.z, x1.w};
#pragma unroll
                for (int j = 0; j < 8; j++)
                    part[j] += w * tanhf(acc[i][j] + xv[j]);
            }
        }
#pragma unroll
        for (int j = 0; j < 8; j++) zred[ty][tx * 8 + j] = part[j];
        __syncthreads();
        float s = 0.f;
#pragma unroll
        for (int q = 0; q < 8; q++) s += zred[q][tid];
        z[(long)b * N + col0 + tid] = s;
    }
}

// ---------------- row softmax, in place -------------------------------------
__global__ void softmax_kernel(float* __restrict__ z, int n)
{
    const int b = blockIdx.x;
    float* row = z + (long)b * n;
    __shared__ float red[256];
    const int tid = threadIdx.x;

    float mx = -1e30f;
    for (int i = tid; i < n; i += 256) mx = fmaxf(mx, row[i]);
    red[tid] = mx; __syncthreads();
    for (int s = 128; s > 0; s >>= 1) {
        if (tid < s) red[tid] = fmaxf(red[tid], red[tid + s]);
        __syncthreads();
    }
    mx = red[0]; __syncthreads();

    float sum = 0.f;
    for (int i = tid; i < n; i += 256) {
        float e = expf(row[i] - mx);
        row[i] = e;
        sum += e;
    }
    red[tid] = sum; __syncthreads();
    for (int s = 128; s > 0; s >>= 1) {
        if (tid < s) red[tid] += red[tid + s];
        __syncthreads();
    }
    float inv = 1.f / red[0];
    for (int i = tid; i < n; i += 256) row[i] *= inv;
}

// ---------------- pooled v: v1[b,d] = sum_m a[b,m] * V[b,d,m] ----------------
__global__ void pool_v_kernel(const float* __restrict__ V,
                              const float* __restrict__ a,
                              float* __restrict__ v1)
{
    const int b = blockIdx.y;
    const int warp = threadIdx.x >> 5;
    const int lane = threadIdx.x & 31;
    const int d = blockIdx.x * 8 + warp;
    const float4* vr = reinterpret_cast<const float4*>(V + ((long)b * D_ + d) * M_);
    const float4* ar = reinterpret_cast<const float4*>(a + (long)b * M_);
    float acc = 0.f;
#pragma unroll
    for (int i = 0; i < M_ / 128; i++) {
        float4 v = vr[i * 32 + lane];
        float4 w = ar[i * 32 + lane];
        acc += v.x * w.x + v.y * w.y + v.z * w.z + v.w * w.w;
    }
#pragma unroll
    for (int o = 16; o > 0; o >>= 1) acc += __shfl_down_sync(0xffffffffu, acc, o);
    if (lane == 0) v1[b * D_ + d] = acc;
}

// ---------------- pooled q: q1[b,d] = sum_l a[b,l] * Q[b,l,d] ----------------
__global__ void pool_q_kernel(const float* __restrict__ Q,
                              const float* __restrict__ a,
                              float* __restrict__ q1)
{
    const int b = blockIdx.x;
    __shared__ float as[L_];
    for (int i = threadIdx.x; i < L_; i += blockDim.x) as[i] = a[b * L_ + i];
    __syncthreads();
    const int d = threadIdx.x;  // blockDim = 512
    const float* qb = Q + (long)b * L_ * D_;
    float acc = 0.f;
#pragma unroll 8
    for (int l = 0; l < L_; l++) acc += as[l] * qb[(long)l * D_ + d];
    q1[b * D_ + d] = acc;
}

// ---------------- broadcast writer: out[b, r, :] = src[b, :] ----------------
__global__ void bcast_kernel(float4* __restrict__ out,
                             const float4* __restrict__ src,
                             int rows)
{
    const long total4 = (long)B_ * rows * (D_ / 4);
    long i = (long)blockIdx.x * blockDim.x + threadIdx.x;
    if (i >= total4) return;
    int d4 = (int)(i % (D_ / 4));
    long br = i / (D_ / 4);
    int b = (int)(br / rows);
    out[i] = __ldg(&src[(long)b * (D_ / 4) + d4]);
}

// ---------------- launch ----------------------------------------------------
extern "C" void kernel_launch(void* const* d_in, const int* in_sizes, int n_in,
                              void* d_out, int out_size)
{
    const float* V   = (const float*)d_in[0];  // [B, D, M]
    const float* Q   = (const float*)d_in[1];  // [B, L, D]
    const float* W_b = (const float*)d_in[2];  // [D, D]
    const float* W_v = (const float*)d_in[3];  // [K, D]
    const float* W_q = (const float*)d_in[4];  // [K, D]
    const float* whv = (const float*)d_in[5];  // [K]
    const float* whq = (const float*)d_in[6];  // [K]
    float* out = (float*)d_out;

    float *p_WqQ, *p_P, *p_Yv, *p_WvV, *p_Yq, *p_R, *p_zv, *p_zq, *p_v1, *p_q1;
    cudaGetSymbolAddress((void**)&p_WqQ, g_WqQ);
    cudaGetSymbolAddress((void**)&p_P,   g_P);
    cudaGetSymbolAddress((void**)&p_Yv,  g_Yv);
    cudaGetSymbolAddress((void**)&p_WvV, g_WvV);
    cudaGetSymbolAddress((void**)&p_Yq,  g_Yq);
    cudaGetSymbolAddress((void**)&p_R,   g_R);
    cudaGetSymbolAddress((void**)&p_zv,  g_zv);
    cudaGetSymbolAddress((void**)&p_zq,  g_zq);
    cudaGetSymbolAddress((void**)&p_v1,  g_v1);
    cudaGetSymbolAddress((void**)&p_q1,  g_q1);

    const long sQ = (long)L_ * D_;      // Q batch stride
    const long sV = (long)D_ * M_;      // V batch stride

    // K1: WqQ[b,k,l] = sum_d W_q[k,d] Q[b,l,d]            (TB, N=256, Kd=512)
    skinny_gemm<true, false><<<dim3(L_ / BNx, B_), 128>>>(
        W_q, Q, p_WqQ, L_, D_, D_, 0, sQ, (long)KK_ * L_,
        nullptr, nullptr, nullptr);

    // K2: P[b,k,e] = sum_l WqQ[b,k,l] Q[b,l,e]            (NN, N=512, Kd=256)
    skinny_gemm<false, false><<<dim3(D_ / BNx, B_), 128>>>(
        p_WqQ, Q, p_P, D_, L_, D_, (long)KK_ * L_, sQ, (long)KK_ * D_,
        nullptr, nullptr, nullptr);

    // K3: Yv[b,k,e] = sum_d P[b,k,d] W_b[d,e]             (NN, N=512, Kd=512)
    skinny_gemm<false, false><<<dim3(D_ / BNx, B_), 128>>>(
        p_P, W_b, p_Yv, D_, D_, D_, (long)KK_ * D_, 0, (long)KK_ * D_,
        nullptr, nullptr, nullptr);

    // K4: WvV[b,k,m] = sum_d W_v[k,d] V[b,d,m]            (NN, N=1024, Kd=512)
    skinny_gemm<false, false><<<dim3(M_ / BNx, B_), 128>>>(
        W_v, V, p_WvV, M_, D_, M_, 0, sV, (long)KK_ * M_,
        nullptr, nullptr, nullptr);

    // K5: Tv = Yv @ V  fused -> z_v = sum_k w*tanh(WvV + Tv)
    skinny_gemm<false, true><<<dim3(M_ / BNx, B_), 128>>>(
        p_Yv, V, nullptr, M_, D_, M_, (long)KK_ * D_, sV, 0,
        p_WvV, whv, p_zv);

    // K6: Yq[b,k,e] = sum_m WvV[b,k,m] V[b,e,m]           (TB, N=512, Kd=1024)
    skinny_gemm<true, false><<<dim3(D_ / BNx, B_), 128>>>(
        p_WvV, V, p_Yq, D_, M_, M_, (long)KK_ * M_, sV, (long)KK_ * D_,
        nullptr, nullptr, nullptr);

    // K7: R[b,k,d] = sum_e Yq[b,k,e] W_b[d,e]             (TB, N=512, Kd=512)
    skinny_gemm<true, false><<<dim3(D_ / BNx, B_), 128>>>(
        p_Yq, W_b, p_R, D_, D_, D_, (long)KK_ * D_, 0, (long)KK_ * D_,
        nullptr, nullptr, nullptr);

    // K8: Tq = R @ Q^T fused -> z_q = sum_k w*tanh(WqQ + Tq)  (TB, N=256)
    skinny_gemm<true, true><<<dim3(L_ / BNx, B_), 128>>>(
        p_R, Q, nullptr, L_, D_, D_, (long)KK_ * D_, sQ, 0,
        p_WqQ, whq, p_zq);

    // softmax
    softmax_kernel<<<B_, 256>>>(p_zv, M_);
    softmax_kernel<<<B_, 256>>>(p_zq, L_);

    // pooled vectors
    {
        dim3 grid(D_ / 8, B_);
        pool_v_kernel<<<grid, 256>>>(V, p_zv, p_v1);
    }
    pool_q_kernel<<<B_, 512>>>(Q, p_zq, p_q1);

    // broadcast to outputs: v [B,M,D] then q [B,L,D]
    {
        long n4v = (long)B_ * M_ * (D_ / 4);
        bcast_kernel<<<(unsigned)((n4v + 255) / 256), 256>>>(
            (float4*)out, (const float4*)p_v1, M_);
        long n4q = (long)B_ * L_ * (D_ / 4);
        float* out_q = out + (long)B_ * M_ * D_;
        bcast_kernel<<<(unsigned)((n4q + 255) / 256), 256>>>(
            (float4*)out_q, (const float4*)p_q1, L_);
    }
}

// round 3
// speedup vs baseline: 2.7413x; 1.1333x over previous
#include <cuda_runtime.h>
#include <math.h>
#include <stdint.h>

// Problem dims (fixed by reference)
#define B_ 64
#define D_ 512
#define M_ 1024
#define L_ 256
#define KK_ 30

#define BKx 32
#define BNx 128
#define ASTR 34                      // even -> LDS.64-aligned pairs, mild 2-way STS conflict
#define A_TILE (BKx * ASTR)          // 1088 floats per A buffer
#define B_TILE (BKx * BNx)           // 4096 floats per B buffer
#define SMEM_FLOATS (2*A_TILE + 2*B_TILE + 4*BNx)   // 10880 floats = 43520 B (<48KB)

// ---------------- scratch (device globals; no allocations allowed) ----------
__device__ float g_WqQ[B_ * KK_ * L_];  // W_q @ Q^T          [B,K,L]
__device__ float g_P  [B_ * KK_ * D_];  // WqQ @ Q            [B,K,D]
__device__ float g_Yv [B_ * KK_ * D_];  // P @ W_b            [B,K,D]
__device__ float g_WvV[B_ * KK_ * M_];  // W_v @ V            [B,K,M]
__device__ float g_Yq [B_ * KK_ * D_];  // WvV @ V^T          [B,K,D]
__device__ float g_R  [B_ * KK_ * D_];  // Yq @ W_b^T         [B,K,D]
__device__ float g_zv [B_ * M_];        // logits / softmax v
__device__ float g_zq [B_ * L_];        // logits / softmax q
__device__ float g_v1 [B_ * D_];        // pooled v
__device__ float g_q1 [B_ * D_];        // pooled q

// ---------------- helpers ----------------------------------------------------
__device__ __forceinline__ uint32_t s2u(const void* p) {
    return (uint32_t)__cvta_generic_to_shared(p);
}
__device__ __forceinline__ void cp16(uint32_t dst, const void* src) {
    asm volatile("cp.async.cg.shared.global [%0], [%1], 16;" :: "r"(dst), "l"(src));
}
__device__ __forceinline__ void cp_commit() { asm volatile("cp.async.commit_group;"); }
__device__ __forceinline__ void cp_wait0()  { asm volatile("cp.async.wait_group 0;"); }

__device__ __forceinline__ unsigned long long pk2(float lo, float hi) {
    unsigned long long r;
    asm("mov.b64 %0, {%1, %2};" : "=l"(r) : "f"(lo), "f"(hi));
    return r;
}
__device__ __forceinline__ void upk2(float& lo, float& hi, unsigned long long v) {
    asm("mov.b64 {%0, %1}, %2;" : "=f"(lo), "=f"(hi) : "l"(v));
}
__device__ __forceinline__ void fma2(unsigned long long& d,
                                     unsigned long long a, unsigned long long b) {
    asm("fma.rn.f32x2 %0, %1, %2, %0;" : "+l"(d) : "l"(a), "l"(b));
}

// ---------------- job descriptor ---------------------------------------------
struct Job {
    const float* A;   // [K(30), Kd] (batched via sA)
    const float* B;   // NN: [Kd][N] ldb ; TB: [N][Kd] ldb
    float* C;         // [K, N] per batch (non-fused)
    const float* X;   // fused: [K, N] bias term
    const float* w;   // fused: [K]
    float* z;         // fused: [N] per batch
    int N, Kd, ldb;
    long sA, sB, sC;  // batch strides (sC also = X stride)
};

// ---------------- skinny GEMM core: C[30,N] = A[30,Kd] @ B --------------------
// Thread layout: 128 threads, ty=warp (4 row-groups of 8), tx=lane (4 cols each).
// acc held as f32x2 pairs over ADJACENT ROWS -> A read is a natural LDS.64.
template<bool TRANS_B, bool FUSE>
__device__ __forceinline__ void gemm_core(const Job j, int tile, float* sm)
{
    float* As = sm;
    float* Bs = sm + 2 * A_TILE;
    float* zr = sm + 2 * A_TILE + 2 * B_TILE;

    const int b    = blockIdx.y;
    const int col0 = tile * BNx;
    const float* Ab = j.A + (long)b * j.sA;
    const float* Bb = j.B + (long)b * j.sB;

    const int tid = threadIdx.x;
    const int tx = tid & 31;
    const int ty = tid >> 5;

    // A staging: thread -> row ar (clamped for pad rows 30,31), 8 k's
    const int ar = tid >> 2;
    const int ac = (tid & 3) * 8;
    const float* aSrc = Ab + (long)(ar < KK_ ? ar : 0) * j.Kd + ac;

    // B NN staging: thread -> k-row bkk, 32-col chunk
    const int bkk = tid >> 2;
    const int bcc = (tid & 3) * 32;
    const float* bNN = Bb + (long)bkk * j.ldb + col0 + bcc;
    // B TB staging: thread -> output col (col0+tid), 32 k's
    const float* bT = Bb + (long)(col0 + tid) * j.ldb;

    float4 a0, a1;
    float4 bt[8];
    const int T = j.Kd / BKx;

    // prologue: stage tile 0
    a0 = *(const float4*)(aSrc);
    a1 = *(const float4*)(aSrc + 4);
    if (!TRANS_B) {
        uint32_t db = s2u(&Bs[bkk * BNx + bcc]);
#pragma unroll
        for (int i = 0; i < 8; i++) cp16(db + i * 16, bNN + i * 4);
        cp_commit();
    } else {
#pragma unroll
        for (int i = 0; i < 8; i++) bt[i] = *(const float4*)(bT + i * 4);
    }

    unsigned long long acc[4][4];
#pragma unroll
    for (int i = 0; i < 4; i++)
#pragma unroll
        for (int jj = 0; jj < 4; jj++) acc[i][jj] = 0ull;  // (0.f, 0.f)

    for (int t = 0; t < T; t++) {
        const int buf = t & 1;
        float* Asb = As + buf * A_TILE;
        float* Bsb = Bs + buf * B_TILE;

        if (!TRANS_B) cp_wait0();
        __syncthreads();  // prev-buf compute finished; cp.async(t) landed

        // STS A transposed: As[kk][row]
        {
            float av[8] = {a0.x, a0.y, a0.z, a0.w, a1.x, a1.y, a1.z, a1.w};
#pragma unroll
            for (int i = 0; i < 8; i++) Asb[(ac + i) * ASTR + ar] = av[i];
        }
        if (TRANS_B) {
#pragma unroll
            for (int i = 0; i < 8; i++) {
                Bsb[(i * 4 + 0) * BNx + tid] = bt[i].x;
                Bsb[(i * 4 + 1) * BNx + tid] = bt[i].y;
                Bsb[(i * 4 + 2) * BNx + tid] = bt[i].z;
                Bsb[(i * 4 + 3) * BNx + tid] = bt[i].w;
            }
        }

        // prefetch tile t+1 into regs / other smem buffer
        if (t + 1 < T) {
            const float* ap = aSrc + (t + 1) * BKx;
            a0 = *(const float4*)ap;
            a1 = *(const float4*)(ap + 4);
            if (!TRANS_B) {
                const float* bp = bNN + (long)(t + 1) * BKx * j.ldb;
                uint32_t db = s2u(&Bs[(buf ^ 1) * B_TILE + bkk * BNx + bcc]);
#pragma unroll
                for (int i = 0; i < 8; i++) cp16(db + i * 16, bp + i * 4);
                cp_commit();
            } else {
                const float* bp = bT + (t + 1) * BKx;
#pragma unroll
                for (int i = 0; i < 8; i++) bt[i] = *(const float4*)(bp + i * 4);
            }
        }
        __syncthreads();  // STS'd tile visible

        // compute tile t: 16 f32x2 per kk per thread (= 32 FMA)
#pragma unroll
        for (int kk = 0; kk < BKx; kk++) {
            const float* arow = Asb + kk * ASTR + ty * 8;
            unsigned long long a2[4];
#pragma unroll
            for (int i = 0; i < 4; i++)
                a2[i] = *(const unsigned long long*)(arow + 2 * i);
            float4 bv = *(const float4*)(Bsb + kk * BNx + tx * 4);
            unsigned long long bd[4] = {pk2(bv.x, bv.x), pk2(bv.y, bv.y),
                                        pk2(bv.z, bv.z), pk2(bv.w, bv.w)};
#pragma unroll
            for (int i = 0; i < 4; i++)
#pragma unroll
                for (int jj = 0; jj < 4; jj++) fma2(acc[i][jj], a2[i], bd[jj]);
        }
    }

    if (!FUSE) {
        float* Cb = j.C + (long)b * j.sC + col0 + tx * 4;
#pragma unroll
        for (int i = 0; i < 4; i++) {
            int r0 = ty * 8 + 2 * i;
            if (r0 < KK_) {  // pair (30,31) skipped; all real pairs fully valid
                float e0, o0, e1, o1, e2, o2, e3, o3;
                upk2(e0, o0, acc[i][0]); upk2(e1, o1, acc[i][1]);
                upk2(e2, o2, acc[i][2]); upk2(e3, o3, acc[i][3]);
                *(float4*)(Cb + (long)r0 * j.N)       = make_float4(e0, e1, e2, e3);
                *(float4*)(Cb + (long)(r0 + 1) * j.N) = make_float4(o0, o1, o2, o3);
            }
        }
    } else {
        float p0 = 0.f, p1 = 0.f, p2 = 0.f, p3 = 0.f;
        const float* Xb = j.X + (long)b * j.sC + col0 + tx * 4;
#pragma unroll
        for (int i = 0; i < 4; i++) {
            int r0 = ty * 8 + 2 * i;
            if (r0 < KK_) {
                float w0 = __ldg(&j.w[r0]), w1 = __ldg(&j.w[r0 + 1]);
                float4 x0 = *(const float4*)(Xb + (long)r0 * j.N);
                float4 x1 = *(const float4*)(Xb + (long)(r0 + 1) * j.N);
                float e, o;
                upk2(e, o, acc[i][0]); p0 += w0 * tanhf(e + x0.x) + w1 * tanhf(o + x1.x);
                upk2(e, o, acc[i][1]); p1 += w0 * tanhf(e + x0.y) + w1 * tanhf(o + x1.y);
                upk2(e, o, acc[i][2]); p2 += w0 * tanhf(e + x0.z) + w1 * tanhf(o + x1.z);
                upk2(e, o, acc[i][3]); p3 += w0 * tanhf(e + x0.w) + w1 * tanhf(o + x1.w);
            }
        }
        *(float4*)(zr + ty * BNx + tx * 4) = make_float4(p0, p1, p2, p3);
        __syncthreads();
        float s = zr[0 * BNx + tid] + zr[1 * BNx + tid]
                + zr[2 * BNx + tid] + zr[3 * BNx + tid];
        j.z[(long)b * j.N + col0 + tid] = s;
    }
}

// Two independent GEMMs fused into one launch (better occupancy, fewer tails)
template<bool T0, bool T1, bool FUSE>
__global__ void __launch_bounds__(128)
pair_gemm(Job j0, Job j1, int tiles0)
{
    extern __shared__ float sm[];
    if ((int)blockIdx.x < tiles0) gemm_core<T0, FUSE>(j0, blockIdx.x, sm);
    else                          gemm_core<T1, FUSE>(j1, blockIdx.x - tiles0, sm);
}

// ---------------- row softmax, in place -------------------------------------
__global__ void softmax_kernel(float* __restrict__ z, int n)
{
    const int b = blockIdx.x;
    float* row = z + (long)b * n;
    __shared__ float red[256];
    const int tid = threadIdx.x;

    float mx = -1e30f;
    for (int i = tid; i < n; i += 256) mx = fmaxf(mx, row[i]);
    red[tid] = mx; __syncthreads();
    for (int s = 128; s > 0; s >>= 1) {
        if (tid < s) red[tid] = fmaxf(red[tid], red[tid + s]);
        __syncthreads();
    }
    mx = red[0]; __syncthreads();

    float sum = 0.f;
    for (int i = tid; i < n; i += 256) {
        float e = expf(row[i] - mx);
        row[i] = e;
        sum += e;
    }
    red[tid] = sum; __syncthreads();
    for (int s = 128; s > 0; s >>= 1) {
        if (tid < s) red[tid] += red[tid + s];
        __syncthreads();
    }
    float inv = 1.f / red[0];
    for (int i = tid; i < n; i += 256) row[i] *= inv;
}

// ---------------- pooled v: v1[b,d] = sum_m a[b,m] * V[b,d,m] ----------------
__global__ void pool_v_kernel(const float* __restrict__ V,
                              const float* __restrict__ a,
                              float* __restrict__ v1)
{
    const int b = blockIdx.y;
    const int warp = threadIdx.x >> 5;
    const int lane = threadIdx.x & 31;
    const int d = blockIdx.x * 8 + warp;
    const float4* vr = reinterpret_cast<const float4*>(V + ((long)b * D_ + d) * M_);
    const float4* ar = reinterpret_cast<const float4*>(a + (long)b * M_);
    float acc = 0.f;
#pragma unroll
    for (int i = 0; i < M_ / 128; i++) {
        float4 v = vr[i * 32 + lane];
        float4 w = ar[i * 32 + lane];
        acc += v.x * w.x + v.y * w.y + v.z * w.z + v.w * w.w;
    }
#pragma unroll
    for (int o = 16; o > 0; o >>= 1) acc += __shfl_down_sync(0xffffffffu, acc, o);
    if (lane == 0) v1[b * D_ + d] = acc;
}

// ---------------- pooled q: q1[b,d] = sum_l a[b,l] * Q[b,l,d] ----------------
__global__ void pool_q_kernel(const float* __restrict__ Q,
                              const float* __restrict__ a,
                              float* __restrict__ q1)
{
    const int b = blockIdx.x;
    __shared__ float as[L_];
    for (int i = threadIdx.x; i < L_; i += blockDim.x) as[i] = a[b * L_ + i];
    __syncthreads();
    const int d = threadIdx.x;  // blockDim = 512
    const float* qb = Q + (long)b * L_ * D_;
    float acc = 0.f;
#pragma unroll 8
    for (int l = 0; l < L_; l++) acc += as[l] * qb[(long)l * D_ + d];
    q1[b * D_ + d] = acc;
}

// ---------------- broadcast writer: out[b, r, :] = src[b, :] ----------------
__global__ void bcast_kernel(float4* __restrict__ out,
                             const float4* __restrict__ src,
                             int rows)
{
    const long total4 = (long)B_ * rows * (D_ / 4);
    long i = (long)blockIdx.x * blockDim.x + threadIdx.x;
    if (i >= total4) return;
    int d4 = (int)(i % (D_ / 4));
    long br = i / (D_ / 4);
    int b = (int)(br / rows);
    out[i] = __ldg(&src[(long)b * (D_ / 4) + d4]);
}

// ---------------- launch ----------------------------------------------------
extern "C" void kernel_launch(void* const* d_in, const int* in_sizes, int n_in,
                              void* d_out, int out_size)
{
    const float* V   = (const float*)d_in[0];  // [B, D, M]
    const float* Q   = (const float*)d_in[1];  // [B, L, D]
    const float* W_b = (const float*)d_in[2];  // [D, D]
    const float* W_v = (const float*)d_in[3];  // [K, D]
    const float* W_q = (const float*)d_in[4];  // [K, D]
    const float* whv = (const float*)d_in[5];  // [K]
    const float* whq = (const float*)d_in[6];  // [K]
    float* out = (float*)d_out;

    float *p_WqQ, *p_P, *p_Yv, *p_WvV, *p_Yq, *p_R, *p_zv, *p_zq, *p_v1, *p_q1;
    cudaGetSymbolAddress((void**)&p_WqQ, g_WqQ);
    cudaGetSymbolAddress((void**)&p_P,   g_P);
    cudaGetSymbolAddress((void**)&p_Yv,  g_Yv);
    cudaGetSymbolAddress((void**)&p_WvV, g_WvV);
    cudaGetSymbolAddress((void**)&p_Yq,  g_Yq);
    cudaGetSymbolAddress((void**)&p_R,   g_R);
    cudaGetSymbolAddress((void**)&p_zv,  g_zv);
    cudaGetSymbolAddress((void**)&p_zq,  g_zq);
    cudaGetSymbolAddress((void**)&p_v1,  g_v1);
    cudaGetSymbolAddress((void**)&p_q1,  g_q1);

    const long sQ = (long)L_ * D_;
    const long sV = (long)D_ * M_;
    const size_t smem = SMEM_FLOATS * sizeof(float);

    Job j0, j1;

    // G1: K4 (NN)  WvV = W_v @ V      |  K1 (TB)  WqQ = W_q @ Q^T
    j0 = {W_v, V, p_WvV, nullptr, nullptr, nullptr, M_, D_, M_, 0, sV, (long)KK_ * M_};
    j1 = {W_q, Q, p_WqQ, nullptr, nullptr, nullptr, L_, D_, D_, 0, sQ, (long)KK_ * L_};
    pair_gemm<false, true, false><<<dim3(M_/BNx + L_/BNx, B_), 128, smem>>>(j0, j1, M_/BNx);

    // G2: K2 (NN)  P = WqQ @ Q        |  K6 (TB)  Yq = WvV @ V^T
    j0 = {p_WqQ, Q, p_P,  nullptr, nullptr, nullptr, D_, L_, D_, (long)KK_ * L_, sQ, (long)KK_ * D_};
    j1 = {p_WvV, V, p_Yq, nullptr, nullptr, nullptr, D_, M_, M_, (long)KK_ * M_, sV, (long)KK_ * D_};
    pair_gemm<false, true, false><<<dim3(D_/BNx + D_/BNx, B_), 128, smem>>>(j0, j1, D_/BNx);

    // G3: K3 (NN)  Yv = P @ W_b       |  K7 (TB)  R = Yq @ W_b^T
    j0 = {p_P,  W_b, p_Yv, nullptr, nullptr, nullptr, D_, D_, D_, (long)KK_ * D_, 0, (long)KK_ * D_};
    j1 = {p_Yq, W_b, p_R,  nullptr, nullptr, nullptr, D_, D_, D_, (long)KK_ * D_, 0, (long)KK_ * D_};
    pair_gemm<false, true, false><<<dim3(D_/BNx + D_/BNx, B_), 128, smem>>>(j0, j1, D_/BNx);

    // G4 (fused logits): K5 (NN) z_v = sum_k w tanh(WvV + Yv@V)
    //                    K8 (TB) z_q = sum_k w tanh(WqQ + R@Q^T)
    j0 = {p_Yv, V, nullptr, p_WvV, whv, p_zv, M_, D_, M_, (long)KK_ * D_, sV, (long)KK_ * M_};
    j1 = {p_R,  Q, nullptr, p_WqQ, whq, p_zq, L_, D_, D_, (long)KK_ * D_, sQ, (long)KK_ * L_};
    pair_gemm<false, true, true><<<dim3(M_/BNx + L_/BNx, B_), 128, smem>>>(j0, j1, M_/BNx);

    // softmax
    softmax_kernel<<<B_, 256>>>(p_zv, M_);
    softmax_kernel<<<B_, 256>>>(p_zq, L_);

    // pooled vectors
    {
        dim3 grid(D_ / 8, B_);
        pool_v_kernel<<<grid, 256>>>(V, p_zv, p_v1);
    }
    pool_q_kernel<<<B_, 512>>>(Q, p_zq, p_q1);

    // broadcast to outputs: v [B,M,D] then q [B,L,D]
    {
        long n4v = (long)B_ * M_ * (D_ / 4);
        bcast_kernel<<<(unsigned)((n4v + 255) / 256), 256>>>(
            (float4*)out, (const float4*)p_v1, M_);
        long n4q = (long)B_ * L_ * (D_ / 4);
        float* out_q = out + (long)B_ * M_ * D_;
        bcast_kernel<<<(unsigned)((n4q + 255) / 256), 256>>>(
            (float4*)out_q, (const float4*)p_q1, L_);
    }
}

// round 4
// speedup vs baseline: 3.0325x; 1.1062x over previous
#include <cuda_runtime.h>
#include <math.h>
#include <stdint.h>

// Problem dims (fixed by reference)
#define B_ 64
#define D_ 512
#define M_ 1024
#define L_ 256
#define KK_ 30

#define BKx 32
#define BNx 128
#define ASTR 34                      // even -> LDS.64-aligned pairs
#define A_TILE (BKx * ASTR)
#define B_TILE (BKx * BNx)
#define SMEM_FLOATS (2*A_TILE + 2*B_TILE)   // 10368 floats = 41472 B -> 5 CTAs/SM

// ---------------- scratch: [2] = split-K partials ----------------------------
#define P_WqQ ((long)B_ * KK_ * L_)
#define P_D   ((long)B_ * KK_ * D_)
#define P_M   ((long)B_ * KK_ * M_)
__device__ float g_WqQ[2 * B_ * KK_ * L_];
__device__ float g_P  [2 * B_ * KK_ * D_];
__device__ float g_Yv [2 * B_ * KK_ * D_];
__device__ float g_WvV[2 * B_ * KK_ * M_];
__device__ float g_Yq [2 * B_ * KK_ * D_];
__device__ float g_R  [2 * B_ * KK_ * D_];
__device__ float g_Tv [2 * B_ * KK_ * M_];
__device__ float g_Tq [2 * B_ * KK_ * L_];
__device__ float g_zv [B_ * M_];
__device__ float g_zq [B_ * L_];
__device__ float g_v1 [B_ * D_];
__device__ float g_q1 [B_ * D_];

// ---------------- helpers ----------------------------------------------------
__device__ __forceinline__ uint32_t s2u(const void* p) {
    return (uint32_t)__cvta_generic_to_shared(p);
}
__device__ __forceinline__ void cp16(uint32_t dst, const void* src) {
    asm volatile("cp.async.cg.shared.global [%0], [%1], 16;" :: "r"(dst), "l"(src));
}
__device__ __forceinline__ void cp_commit() { asm volatile("cp.async.commit_group;"); }
__device__ __forceinline__ void cp_wait0()  { asm volatile("cp.async.wait_group 0;"); }

__device__ __forceinline__ unsigned long long pk2(float lo, float hi) {
    unsigned long long r;
    asm("mov.b64 %0, {%1, %2};" : "=l"(r) : "f"(lo), "f"(hi));
    return r;
}
__device__ __forceinline__ void upk2(float& lo, float& hi, unsigned long long v) {
    asm("mov.b64 {%0, %1}, %2;" : "=f"(lo), "=f"(hi) : "l"(v));
}
__device__ __forceinline__ void fma2(unsigned long long& d,
                                     unsigned long long a, unsigned long long b) {
    asm("fma.rn.f32x2 %0, %1, %2, %0;" : "+l"(d) : "l"(a), "l"(b));
}

// ---------------- job descriptor ---------------------------------------------
struct Job {
    const float* A0;  // [K(30), Kd], batched via sA
    const float* A1;  // second split-partial of A (same layout) or nullptr
    const float* B;   // NN: [Kd][N] ldb ; TB: [N][Kd] ldb
    float* C;         // partial-0 base; partial-1 at C + partC
    int N, Kd, ldb;
    long sA, sB, sC;
    long partC;       // stride between split partial buffers
};

// ---------------- skinny GEMM core: Cpart[30,N] = A[30,Kd/2] @ Bhalf ----------
template<bool TRANS_B>
__device__ __forceinline__ void gemm_core(const Job j, int tile, int split, float* sm)
{
    float* As = sm;
    float* Bs = sm + 2 * A_TILE;

    const int b    = blockIdx.y;
    const int col0 = tile * BNx;
    const float* Ab0 = j.A0 + (long)b * j.sA;
    const float* Ab1 = j.A1 ? (j.A1 + (long)b * j.sA) : nullptr;
    const float* Bb  = j.B + (long)b * j.sB;

    const int tid = threadIdx.x;
    const int tx = tid & 31;
    const int ty = tid >> 5;

    // A staging: thread -> row ar (clamped for pad rows), 8 k's
    const int ar = tid >> 2;
    const int ac = (tid & 3) * 8;
    const long aOff = (long)(ar < KK_ ? ar : 0) * j.Kd + ac;

    // B NN staging: thread -> k-row bkk, 32-col chunk
    const int bkk = tid >> 2;
    const int bcc = (tid & 3) * 32;
    const float* bNN = Bb + (long)bkk * j.ldb + col0 + bcc;
    // B TB staging: thread -> output col (col0+tid), 32 k's
    const float* bT = Bb + (long)(col0 + tid) * j.ldb;

    const int Tall   = j.Kd / BKx;
    const int tFirst = split * (Tall / 2);
    const int tLast  = tFirst + (Tall / 2);

    float4 a0, a1;
    float4 bt[8];

    // prologue: stage tile tFirst
    {
        const float* ap = Ab0 + aOff + tFirst * BKx;
        a0 = *(const float4*)(ap);
        a1 = *(const float4*)(ap + 4);
        if (Ab1) {
            const float* aq = Ab1 + aOff + tFirst * BKx;
            float4 c0 = *(const float4*)(aq);
            float4 c1 = *(const float4*)(aq + 4);
            a0.x += c0.x; a0.y += c0.y; a0.z += c0.z; a0.w += c0.w;
            a1.x += c1.x; a1.y += c1.y; a1.z += c1.z; a1.w += c1.w;
        }
    }
    if (!TRANS_B) {
        const float* bp = bNN + (long)tFirst * BKx * j.ldb;
        uint32_t db = s2u(&Bs[bkk * BNx + bcc]);
#pragma unroll
        for (int i = 0; i < 8; i++) cp16(db + i * 16, bp + i * 4);
        cp_commit();
    } else {
        const float* bp = bT + tFirst * BKx;
#pragma unroll
        for (int i = 0; i < 8; i++) bt[i] = *(const float4*)(bp + i * 4);
    }

    unsigned long long acc[4][4];
#pragma unroll
    for (int i = 0; i < 4; i++)
#pragma unroll
        for (int jj = 0; jj < 4; jj++) acc[i][jj] = 0ull;

    for (int t = tFirst; t < tLast; t++) {
        const int buf = t & 1;
        float* Asb = As + buf * A_TILE;
        float* Bsb = Bs + buf * B_TILE;

        if (!TRANS_B) cp_wait0();
        __syncthreads();

        // STS A transposed: As[kk][row]
        {
            float av[8] = {a0.x, a0.y, a0.z, a0.w, a1.x, a1.y, a1.z, a1.w};
#pragma unroll
            for (int i = 0; i < 8; i++) Asb[(ac + i) * ASTR + ar] = av[i];
        }
        if (TRANS_B) {
#pragma unroll
            for (int i = 0; i < 8; i++) {
                Bsb[(i * 4 + 0) * BNx + tid] = bt[i].x;
                Bsb[(i * 4 + 1) * BNx + tid] = bt[i].y;
                Bsb[(i * 4 + 2) * BNx + tid] = bt[i].z;
                Bsb[(i * 4 + 3) * BNx + tid] = bt[i].w;
            }
        }

        // prefetch tile t+1
        if (t + 1 < tLast) {
            const float* ap = Ab0 + aOff + (t + 1) * BKx;
            a0 = *(const float4*)ap;
            a1 = *(const float4*)(ap + 4);
            if (Ab1) {
                const float* aq = Ab1 + aOff + (t + 1) * BKx;
                float4 c0 = *(const float4*)(aq);
                float4 c1 = *(const float4*)(aq + 4);
                a0.x += c0.x; a0.y += c0.y; a0.z += c0.z; a0.w += c0.w;
                a1.x += c1.x; a1.y += c1.y; a1.z += c1.z; a1.w += c1.w;
            }
            if (!TRANS_B) {
                const float* bp = bNN + (long)(t + 1) * BKx * j.ldb;
                uint32_t db = s2u(&Bs[(buf ^ 1) * B_TILE + bkk * BNx + bcc]);
#pragma unroll
                for (int i = 0; i < 8; i++) cp16(db + i * 16, bp + i * 4);
                cp_commit();
            } else {
                const float* bp = bT + (t + 1) * BKx;
#pragma unroll
                for (int i = 0; i < 8; i++) bt[i] = *(const float4*)(bp + i * 4);
            }
        }
        __syncthreads();

        // compute tile t: 16 f32x2 per kk per thread (= 32 FMA)
#pragma unroll
        for (int kk = 0; kk < BKx; kk++) {
            const float* arow = Asb + kk * ASTR + ty * 8;
            unsigned long long a2[4];
#pragma unroll
            for (int i = 0; i < 4; i++)
                a2[i] = *(const unsigned long long*)(arow + 2 * i);
            float4 bv = *(const float4*)(Bsb + kk * BNx + tx * 4);
            unsigned long long bd[4] = {pk2(bv.x, bv.x), pk2(bv.y, bv.y),
                                        pk2(bv.z, bv.z), pk2(bv.w, bv.w)};
#pragma unroll
            for (int i = 0; i < 4; i++)
#pragma unroll
                for (int jj = 0; jj < 4; jj++) fma2(acc[i][jj], a2[i], bd[jj]);
        }
    }

    float* Cb = j.C + (long)split * j.partC + (long)b * j.sC + col0 + tx * 4;
#pragma unroll
    for (int i = 0; i < 4; i++) {
        int r0 = ty * 8 + 2 * i;
        if (r0 < KK_) {
            float e0, o0, e1, o1, e2, o2, e3, o3;
            upk2(e0, o0, acc[i][0]); upk2(e1, o1, acc[i][1]);
            upk2(e2, o2, acc[i][2]); upk2(e3, o3, acc[i][3]);
            *(float4*)(Cb + (long)r0 * j.N)       = make_float4(e0, e1, e2, e3);
            *(float4*)(Cb + (long)(r0 + 1) * j.N) = make_float4(o0, o1, o2, o3);
        }
    }
}

// Two independent GEMMs (x2 K-splits each) in one launch
template<bool T0, bool T1>
__global__ void __launch_bounds__(128, 5)
pair_gemm(Job j0, Job j1, int tiles0, int tiles1)
{
    extern __shared__ float sm[];
    int bx = blockIdx.x;
    int n0 = tiles0 * 2;
    if (bx < n0) gemm_core<T0>(j0, bx % tiles0, bx / tiles0, sm);
    else {
        int l = bx - n0;
        gemm_core<T1>(j1, l % tiles1, l / tiles1, sm);
    }
}

// ---------------- logits: z = sum_k w[k]*tanh(X0+X1+T0+T1) -------------------
__global__ void logits_kernel(const float* __restrict__ X0, const float* __restrict__ X1,
                              const float* __restrict__ T0, const float* __restrict__ T1,
                              const float* __restrict__ w,
                              float* __restrict__ z, int n)
{
    int idx = blockIdx.x * blockDim.x + threadIdx.x;
    if (idx >= B_ * n) return;
    int b = idx / n;
    int m = idx - b * n;
    long base = (long)b * KK_ * n + m;
    float acc = 0.f;
#pragma unroll
    for (int k = 0; k < KK_; k++) {
        long o = base + (long)k * n;
        acc += __ldg(&w[k]) * tanhf(X0[o] + X1[o] + T0[o] + T1[o]);
    }
    z[idx] = acc;
}

// ---------------- row softmax, in place -------------------------------------
__global__ void softmax_kernel(float* __restrict__ z, int n)
{
    const int b = blockIdx.x;
    float* row = z + (long)b * n;
    __shared__ float red[256];
    const int tid = threadIdx.x;

    float mx = -1e30f;
    for (int i = tid; i < n; i += 256) mx = fmaxf(mx, row[i]);
    red[tid] = mx; __syncthreads();
    for (int s = 128; s > 0; s >>= 1) {
        if (tid < s) red[tid] = fmaxf(red[tid], red[tid + s]);
        __syncthreads();
    }
    mx = red[0]; __syncthreads();

    float sum = 0.f;
    for (int i = tid; i < n; i += 256) {
        float e = expf(row[i] - mx);
        row[i] = e;
        sum += e;
    }
    red[tid] = sum; __syncthreads();
    for (int s = 128; s > 0; s >>= 1) {
        if (tid < s) red[tid] += red[tid + s];
        __syncthreads();
    }
    float inv = 1.f / red[0];
    for (int i = tid; i < n; i += 256) row[i] *= inv;
}

// ---------------- pooled v: v1[b,d] = sum_m a[b,m] * V[b,d,m] ----------------
__global__ void pool_v_kernel(const float* __restrict__ V,
                              const float* __restrict__ a,
                              float* __restrict__ v1)
{
    const int b = blockIdx.y;
    const int warp = threadIdx.x >> 5;
    const int lane = threadIdx.x & 31;
    const int d = blockIdx.x * 8 + warp;
    const float4* vr = reinterpret_cast<const float4*>(V + ((long)b * D_ + d) * M_);
    const float4* ar = reinterpret_cast<const float4*>(a + (long)b * M_);
    float acc = 0.f;
#pragma unroll
    for (int i = 0; i < M_ / 128; i++) {
        float4 v = vr[i * 32 + lane];
        float4 w = ar[i * 32 + lane];
        acc += v.x * w.x + v.y * w.y + v.z * w.z + v.w * w.w;
    }
#pragma unroll
    for (int o = 16; o > 0; o >>= 1) acc += __shfl_down_sync(0xffffffffu, acc, o);
    if (lane == 0) v1[b * D_ + d] = acc;
}

// ---------------- pooled q: q1[b,d] = sum_l a[b,l] * Q[b,l,d] ----------------
__global__ void pool_q_kernel(const float* __restrict__ Q,
                              const float* __restrict__ a,
                              float* __restrict__ q1)
{
    const int b = blockIdx.x;
    __shared__ float as[L_];
    for (int i = threadIdx.x; i < L_; i += blockDim.x) as[i] = a[b * L_ + i];
    __syncthreads();
    const int d = threadIdx.x;  // blockDim = 512
    const float* qb = Q + (long)b * L_ * D_;
    float acc = 0.f;
#pragma unroll 8
    for (int l = 0; l < L_; l++) acc += as[l] * qb[(long)l * D_ + d];
    q1[b * D_ + d] = acc;
}

// ---------------- broadcast writer: out[b, r, :] = src[b, :] ----------------
__global__ void bcast_kernel(float4* __restrict__ out,
                             const float4* __restrict__ src,
                             int rows)
{
    const long total4 = (long)B_ * rows * (D_ / 4);
    long i = (long)blockIdx.x * blockDim.x + threadIdx.x;
    if (i >= total4) return;
    int d4 = (int)(i % (D_ / 4));
    long br = i / (D_ / 4);
    int b = (int)(br / rows);
    out[i] = __ldg(&src[(long)b * (D_ / 4) + d4]);
}

// ---------------- launch ----------------------------------------------------
extern "C" void kernel_launch(void* const* d_in, const int* in_sizes, int n_in,
                              void* d_out, int out_size)
{
    const float* V   = (const float*)d_in[0];  // [B, D, M]
    const float* Q   = (const float*)d_in[1];  // [B, L, D]
    const float* W_b = (const float*)d_in[2];  // [D, D]
    const float* W_v = (const float*)d_in[3];  // [K, D]
    const float* W_q = (const float*)d_in[4];  // [K, D]
    const float* whv = (const float*)d_in[5];  // [K]
    const float* whq = (const float*)d_in[6];  // [K]
    float* out = (float*)d_out;

    float *p_WqQ, *p_P, *p_Yv, *p_WvV, *p_Yq, *p_R, *p_Tv, *p_Tq;
    float *p_zv, *p_zq, *p_v1, *p_q1;
    cudaGetSymbolAddress((void**)&p_WqQ, g_WqQ);
    cudaGetSymbolAddress((void**)&p_P,   g_P);
    cudaGetSymbolAddress((void**)&p_Yv,  g_Yv);
    cudaGetSymbolAddress((void**)&p_WvV, g_WvV);
    cudaGetSymbolAddress((void**)&p_Yq,  g_Yq);
    cudaGetSymbolAddress((void**)&p_R,   g_R);
    cudaGetSymbolAddress((void**)&p_Tv,  g_Tv);
    cudaGetSymbolAddress((void**)&p_Tq,  g_Tq);
    cudaGetSymbolAddress((void**)&p_zv,  g_zv);
    cudaGetSymbolAddress((void**)&p_zq,  g_zq);
    cudaGetSymbolAddress((void**)&p_v1,  g_v1);
    cudaGetSymbolAddress((void**)&p_q1,  g_q1);

    const long sQ = (long)L_ * D_;
    const long sV = (long)D_ * M_;
    const size_t smem = SMEM_FLOATS * sizeof(float);

    Job j0, j1;

    // G1: K4 (NN)  WvV = W_v @ V      |  K1 (TB)  WqQ = W_q @ Q^T
    j0 = {W_v, nullptr, V, p_WvV, M_, D_, M_, 0, sV, (long)KK_ * M_, P_M};
    j1 = {W_q, nullptr, Q, p_WqQ, L_, D_, D_, 0, sQ, (long)KK_ * L_, P_WqQ};
    pair_gemm<false, true><<<dim3(2*(M_/BNx) + 2*(L_/BNx), B_), 128, smem>>>(
        j0, j1, M_/BNx, L_/BNx);

    // G2: K2 (NN)  P = WqQ @ Q        |  K6 (TB)  Yq = WvV @ V^T
    j0 = {p_WqQ, p_WqQ + P_WqQ, Q, p_P,  D_, L_, D_, (long)KK_ * L_, sQ, (long)KK_ * D_, P_D};
    j1 = {p_WvV, p_WvV + P_M,   V, p_Yq, D_, M_, M_, (long)KK_ * M_, sV, (long)KK_ * D_, P_D};
    pair_gemm<false, true><<<dim3(4*(D_/BNx), B_), 128, smem>>>(j0, j1, D_/BNx, D_/BNx);

    // G3: K3 (NN)  Yv = P @ W_b       |  K7 (TB)  R = Yq @ W_b^T
    j0 = {p_P,  p_P + P_D,  W_b, p_Yv, D_, D_, D_, (long)KK_ * D_, 0, (long)KK_ * D_, P_D};
    j1 = {p_Yq, p_Yq + P_D, W_b, p_R,  D_, D_, D_, (long)KK_ * D_, 0, (long)KK_ * D_, P_D};
    pair_gemm<false, true><<<dim3(4*(D_/BNx), B_), 128, smem>>>(j0, j1, D_/BNx, D_/BNx);

    // G4: K5 (NN)  Tv = Yv @ V        |  K8 (TB)  Tq = R @ Q^T
    j0 = {p_Yv, p_Yv + P_D, V, p_Tv, M_, D_, M_, (long)KK_ * D_, sV, (long)KK_ * M_, P_M};
    j1 = {p_R,  p_R + P_D,  Q, p_Tq, L_, D_, D_, (long)KK_ * D_, sQ, (long)KK_ * L_, P_WqQ};
    pair_gemm<false, true><<<dim3(2*(M_/BNx) + 2*(L_/BNx), B_), 128, smem>>>(
        j0, j1, M_/BNx, L_/BNx);

    // logits: z = sum_k w*tanh(X0+X1+T0+T1)
    logits_kernel<<<(B_ * M_ + 255) / 256, 256>>>(
        p_WvV, p_WvV + P_M, p_Tv, p_Tv + P_M, whv, p_zv, M_);
    logits_kernel<<<(B_ * L_ + 255) / 256, 256>>>(
        p_WqQ, p_WqQ + P_WqQ, p_Tq, p_Tq + P_WqQ, whq, p_zq, L_);

    // softmax
    softmax_kernel<<<B_, 256>>>(p_zv, M_);
    softmax_kernel<<<B_, 256>>>(p_zq, L_);

    // pooled vectors
    {
        dim3 grid(D_ / 8, B_);
        pool_v_kernel<<<grid, 256>>>(V, p_zv, p_v1);
    }
    pool_q_kernel<<<B_, 512>>>(Q, p_zq, p_q1);

    // broadcast to outputs: v [B,M,D] then q [B,L,D]
    {
        long n4v = (long)B_ * M_ * (D_ / 4);
        bcast_kernel<<<(unsigned)((n4v + 255) / 256), 256>>>(
            (float4*)out, (const float4*)p_v1, M_);
        long n4q = (long)B_ * L_ * (D_ / 4);
        float* out_q = out + (long)B_ * M_ * D_;
        bcast_kernel<<<(unsigned)((n4q + 255) / 256), 256>>>(
            (float4*)out_q, (const float4*)p_q1, L_);
    }
}

// round 6
// speedup vs baseline: 4.0720x; 1.3428x over previous
#include <cuda_runtime.h>
#include <cuda_bf16.h>
#include <math.h>
#include <stdint.h>

// Problem dims (fixed)
#define B_ 64
#define D_ 512
#define M_ 1024
#define L_ 256
#define KK_ 30

typedef __nv_bfloat16 bf16;

// ===================== device scratch (no allocs allowed) ====================
__device__ bf16 g_Vt_hi[(long)B_ * M_ * D_];   // [B][M][D]
__device__ bf16 g_Vt_lo[(long)B_ * M_ * D_];
__device__ bf16 g_Vn_hi[(long)B_ * D_ * M_];   // [B][D][M]
__device__ bf16 g_Vn_lo[(long)B_ * D_ * M_];
__device__ bf16 g_Qn_hi[(long)B_ * L_ * D_];   // [B][L][D]
__device__ bf16 g_Qn_lo[(long)B_ * L_ * D_];
__device__ bf16 g_Qt_hi[(long)B_ * D_ * L_];   // [B][D][L]
__device__ bf16 g_Qt_lo[(long)B_ * D_ * L_];
__device__ bf16 g_Wbn_hi[D_ * D_];
__device__ bf16 g_Wbn_lo[D_ * D_];
__device__ bf16 g_Wbt_hi[D_ * D_];
__device__ bf16 g_Wbt_lo[D_ * D_];
__device__ bf16 g_Wv_hi[32 * D_];
__device__ bf16 g_Wv_lo[32 * D_];
__device__ bf16 g_Wq_hi[32 * D_];
__device__ bf16 g_Wq_lo[32 * D_];
__device__ bf16 g_WqQ_hi[(long)B_ * 32 * L_];
__device__ bf16 g_WqQ_lo[(long)B_ * 32 * L_];
__device__ float g_WqQ_f[(long)B_ * 32 * L_];
__device__ bf16 g_P_hi[(long)B_ * 32 * D_];
__device__ bf16 g_P_lo[(long)B_ * 32 * D_];
__device__ bf16 g_Yv_hi[(long)B_ * 32 * D_];
__device__ bf16 g_Yv_lo[(long)B_ * 32 * D_];
__device__ bf16 g_WvV_hi[(long)B_ * 32 * M_];
__device__ bf16 g_WvV_lo[(long)B_ * 32 * M_];
__device__ bf16 g_Yq_hi[(long)B_ * 32 * D_];
__device__ bf16 g_Yq_lo[(long)B_ * 32 * D_];
__device__ bf16 g_R_hi[(long)B_ * 32 * D_];
__device__ bf16 g_R_lo[(long)B_ * 32 * D_];
__device__ float g_zv[B_ * M_];
__device__ float g_zq[B_ * L_];
__device__ float g_v1[B_ * D_];
__device__ float g_q1[B_ * D_];

// ===================== helpers ================================================
__device__ __forceinline__ uint32_t s2u(const void* p) {
    return (uint32_t)__cvta_generic_to_shared(p);
}
__device__ __forceinline__ void cp16(uint32_t dst, const void* src) {
    asm volatile("cp.async.cg.shared.global [%0], [%1], 16;" :: "r"(dst), "l"(src));
}
__device__ __forceinline__ void cp_commit() { asm volatile("cp.async.commit_group;"); }
__device__ __forceinline__ void cp_wait0()  { asm volatile("cp.async.wait_group 0;"); }

__device__ __forceinline__ void ldsm4(uint32_t* r, uint32_t addr) {
    asm volatile("ldmatrix.sync.aligned.m8n8.x4.shared.b16 {%0,%1,%2,%3}, [%4];"
                 : "=r"(r[0]), "=r"(r[1]), "=r"(r[2]), "=r"(r[3]) : "r"(addr));
}
__device__ __forceinline__ void mma_bf(float* d, const uint32_t* a, const uint32_t* b) {
    asm volatile(
        "mma.sync.aligned.m16n8k16.row.col.f32.bf16.bf16.f32 "
        "{%0,%1,%2,%3}, {%4,%5,%6,%7}, {%8,%9}, {%0,%1,%2,%3};"
        : "+f"(d[0]), "+f"(d[1]), "+f"(d[2]), "+f"(d[3])
        : "r"(a[0]), "r"(a[1]), "r"(a[2]), "r"(a[3]), "r"(b[0]), "r"(b[1]));
}

__device__ __forceinline__ void split_bf(float x, bf16& h, bf16& l) {
    h = __float2bfloat16(x);
    l = __float2bfloat16(x - __bfloat162float(h));
}
__device__ __forceinline__ uint32_t pkbf(float a, float b) {
    __nv_bfloat162 t = __floats2bfloat162_rn(a, b);
    return *(uint32_t*)&t;
}

// smem layout constants (bytes)
#define A_BUF 10240               // 128 x 40 bf16 (one hl, one buf)
#define B_BUF 2560                // 32 x 40 bf16
#define BS_OFF 40960u             // after 4 A buffers
#define CST 132                   // Cs n-stride (floats), conflict-free

// ===================== conversion kernels =====================================
__global__ void conv_trans(const float* __restrict__ X,
                           bf16* __restrict__ Nh, bf16* __restrict__ Nl,
                           bf16* __restrict__ Th, bf16* __restrict__ Tl,
                           int R, int C, long sX)
{
    __shared__ float t[32][33];
    const int b = blockIdx.z;
    const float* Xb = X + (long)b * sX;
    const int c0 = blockIdx.x * 32, r0 = blockIdx.y * 32;
    const int tx = threadIdx.x, ty = threadIdx.y;

#pragma unroll
    for (int i = 0; i < 4; i++) {
        int r = r0 + ty + i * 8;
        float v = Xb[(long)r * C + c0 + tx];
        t[ty + i * 8][tx] = v;
        bf16 h, l; split_bf(v, h, l);
        long o = (long)b * R * C + (long)r * C + c0 + tx;
        Nh[o] = h; Nl[o] = l;
    }
    __syncthreads();
#pragma unroll
    for (int i = 0; i < 4; i++) {
        int c = c0 + ty + i * 8;
        float v = t[tx][ty + i * 8];
        bf16 h, l; split_bf(v, h, l);
        long o = (long)b * C * R + (long)c * R + r0 + tx;
        Th[o] = h; Tl[o] = l;
    }
}

__global__ void conv_pad(const float* __restrict__ Wv, bf16* __restrict__ Vh, bf16* __restrict__ Vl,
                         const float* __restrict__ Wq, bf16* __restrict__ Qh, bf16* __restrict__ Ql)
{
    int idx = blockIdx.x * blockDim.x + threadIdx.x;
    if (idx >= 32 * D_) return;
    int k = idx / D_, d = idx % D_;
    float a = (k < KK_) ? Wv[k * D_ + d] : 0.f;
    float b = (k < KK_) ? Wq[k * D_ + d] : 0.f;
    bf16 h, l;
    split_bf(a, h, l); Vh[idx] = h; Vl[idx] = l;
    split_bf(b, h, l); Qh[idx] = h; Ql[idx] = l;
}

// ===================== HMMA GEMM ==============================================
// Ct[tile of 128 rows of Nbig][32] = A[Nbig,Kd] x S[32,Kd]^T, bf16 hi/lo split.
struct GJob {
    const bf16 *Ah, *Al;                 // big operand (row-major [Nbig][Kd]), batch stride sA
    const bf16 *B0h, *B0l, *B1h, *B1l;   // small operands [32][Kd]
    bf16 *Ch, *Cl;                       // out [b][32][Nbig]
    float* Cf;                           // EPI1: fp32 out; EPI3: fp32 X in
    const float* w;                      // logits weights (EPI 2/3)
    float* z;                            // logits out [b][Nbig] (EPI 2/3)
    int Nbig, Kd;
    long sA, sB0, sB1;
};

// EPI: 0 = hi/lo out; 1 = hi/lo + fp32 out; 2 = (NB=2) hi/lo of acc0 + logits(acc0+acc1);
//      3 = logits(acc0 + fp32 X)
template<int NB, int EPI>
__global__ void __launch_bounds__(256) tc_gemm(GJob j)
{
    extern __shared__ char smem[];
    const uint32_t sb = s2u(smem);
    float* smw = (float*)(smem + BS_OFF + NB * 2 * 2 * B_BUF);

    const int tid = threadIdx.x;
    const int w = tid >> 5, lane = tid & 31;
    const int b = blockIdx.y;
    const int m0 = blockIdx.x * 128;

    const bf16* Ab[2] = { j.Ah + (long)b * j.sA, j.Al + (long)b * j.sA };
    const bf16* Bb[2][2];
    Bb[0][0] = j.B0h + (long)b * j.sB0;
    Bb[0][1] = j.B0l + (long)b * j.sB0;
    if (NB == 2) {
        Bb[1][0] = j.B1h + (long)b * j.sB1;
        Bb[1][1] = j.B1l + (long)b * j.sB1;
    }

    if (EPI >= 2 && tid < KK_) smw[tid] = j.w[tid];

    // staging indices
    const int ar = tid >> 1, ac2 = tid & 1;       // A: row, 32B-chunk
    const int bhl = tid >> 7, bi = tid & 127;     // B: hi/lo, chunk
    const int br = bi >> 2, bc = bi & 3;

    const int T = j.Kd / 32;

    auto stage = [&](int t) {
        const int s = t & 1;
#pragma unroll
        for (int hl = 0; hl < 2; hl++) {
            uint32_t dst = sb + (uint32_t)((s * 2 + hl) * A_BUF) + ar * 80 + ac2 * 32;
            const bf16* src = Ab[hl] + (long)(m0 + ar) * j.Kd + t * 32 + ac2 * 16;
            cp16(dst, src);
            cp16(dst + 16, src + 8);
        }
#pragma unroll
        for (int nb = 0; nb < NB; nb++) {
            uint32_t dst = sb + BS_OFF + (uint32_t)(((s * NB + nb) * 2 + bhl) * B_BUF)
                         + br * 80 + bc * 16;
            cp16(dst, Bb[nb][bhl] + (long)br * j.Kd + t * 32 + bc * 8);
        }
        cp_commit();
    };

    float acc[NB][4][4];
#pragma unroll
    for (int nb = 0; nb < NB; nb++)
#pragma unroll
        for (int nt = 0; nt < 4; nt++)
#pragma unroll
            for (int r = 0; r < 4; r++) acc[nb][nt][r] = 0.f;

    // ldmatrix lane addressing (constant parts)
    const uint32_t aLane = (uint32_t)((w * 16 + (lane & 15)) * 80 + (lane >> 4) * 16);
    const uint32_t bLaneRow = (uint32_t)((((lane >> 4) & 1) * 8 + (lane & 7)) * 80
                                         + ((lane >> 3) & 1) * 16);

    stage(0);

    for (int t = 0; t < T; t++) {
        const int s = t & 1;
        cp_wait0();
        __syncthreads();

        if (t + 1 < T) stage(t + 1);

        const uint32_t aH = sb + (uint32_t)((s * 2 + 0) * A_BUF) + aLane;
        const uint32_t aL = aH + A_BUF;

#pragma unroll
        for (int ks = 0; ks < 2; ks++) {
            uint32_t ah[4], al[4];
            ldsm4(ah, aH + ks * 32);
            ldsm4(al, aL + ks * 32);
#pragma unroll
            for (int nb = 0; nb < NB; nb++) {
#pragma unroll
                for (int p = 0; p < 2; p++) {
                    uint32_t bbase = sb + BS_OFF
                        + (uint32_t)(((s * NB + nb) * 2 + 0) * B_BUF)
                        + (uint32_t)(p * 16 * 80) + bLaneRow + ks * 32;
                    uint32_t bh[4], bl[4];
                    ldsm4(bh, bbase);
                    ldsm4(bl, bbase + B_BUF);
                    mma_bf(acc[nb][2 * p],     ah, &bh[0]);
                    mma_bf(acc[nb][2 * p],     ah, &bl[0]);
                    mma_bf(acc[nb][2 * p],     al, &bh[0]);
                    mma_bf(acc[nb][2 * p + 1], ah, &bh[2]);
                    mma_bf(acc[nb][2 * p + 1], ah, &bl[2]);
                    mma_bf(acc[nb][2 * p + 1], al, &bh[2]);
                }
            }
        }
    }

    // ---------------- epilogue: stage accs in smem (reuses A region) ---------
    __syncthreads();
    float* Cs = (float*)smem;
    {
        const int g = lane >> 2, cc = lane & 3;
        const int m_l = w * 16 + g;
#pragma unroll
        for (int nb = 0; nb < NB; nb++) {
            float* C_ = Cs + nb * 32 * CST;
#pragma unroll
            for (int nt = 0; nt < 4; nt++) {
                int n0 = nt * 8 + cc * 2;
                C_[(n0 + 0) * CST + m_l]     = acc[nb][nt][0];
                C_[(n0 + 1) * CST + m_l]     = acc[nb][nt][1];
                C_[(n0 + 0) * CST + m_l + 8] = acc[nb][nt][2];
                C_[(n0 + 1) * CST + m_l + 8] = acc[nb][nt][3];
            }
        }
    }
    __syncthreads();

    if (EPI != 3) {
        // write acc0 tile -> Ch/Cl (+Cf for EPI1), coalesced
#pragma unroll
        for (int it = 0; it < 4; it++) {
            int q = tid + it * 256;        // 1024 quads of 4 m's
            int n = q >> 5, m4 = (q & 31) * 4;
            float4 v = *(float4*)&Cs[n * CST + m4];
            bf16 h0, l0, h1, l1, h2, l2, h3, l3;
            split_bf(v.x, h0, l0); split_bf(v.y, h1, l1);
            split_bf(v.z, h2, l2); split_bf(v.w, h3, l3);
            long o = ((long)b * 32 + n) * j.Nbig + m0 + m4;
            *(uint2*)(j.Ch + o) = make_uint2(
                ((uint32_t)*(uint16_t*)&h0) | ((uint32_t)*(uint16_t*)&h1 << 16),
                ((uint32_t)*(uint16_t*)&h2) | ((uint32_t)*(uint16_t*)&h3 << 16));
            *(uint2*)(j.Cl + o) = make_uint2(
                ((uint32_t)*(uint16_t*)&l0) | ((uint32_t)*(uint16_t*)&l1 << 16),
                ((uint32_t)*(uint16_t*)&l2) | ((uint32_t)*(uint16_t*)&l3 << 16));
            if (EPI == 1) *(float4*)(j.Cf + o) = v;
        }
    }
    if (EPI == 2) {
        if (tid < 128) {
            float zacc = 0.f;
#pragma unroll
            for (int k = 0; k < KK_; k++)
                zacc += smw[k] * tanhf(Cs[k * CST + tid] + Cs[(32 + k) * CST + tid]);
            j.z[(long)b * j.Nbig + m0 + tid] = zacc;
        }
    }
    if (EPI == 3) {
        if (tid < 128) {
            const float* X = j.Cf + (long)b * 32 * j.Nbig + m0 + tid;
            float zacc = 0.f;
#pragma unroll
            for (int k = 0; k < KK_; k++)
                zacc += smw[k] * tanhf(Cs[k * CST + tid] + X[(long)k * j.Nbig]);
            j.z[(long)b * j.Nbig + m0 + tid] = zacc;
        }
    }
}

// ===================== tail kernels ===========================================
__global__ void softmax_kernel(float* __restrict__ z, int n)
{
    const int b = blockIdx.x;
    float* row = z + (long)b * n;
    __shared__ float red[256];
    const int tid = threadIdx.x;

    float mx = -1e30f;
    for (int i = tid; i < n; i += 256) mx = fmaxf(mx, row[i]);
    red[tid] = mx; __syncthreads();
    for (int s = 128; s > 0; s >>= 1) {
        if (tid < s) red[tid] = fmaxf(red[tid], red[tid + s]);
        __syncthreads();
    }
    mx = red[0]; __syncthreads();

    float sum = 0.f;
    for (int i = tid; i < n; i += 256) {
        float e = expf(row[i] - mx);
        row[i] = e;
        sum += e;
    }
    red[tid] = sum; __syncthreads();
    for (int s = 128; s > 0; s >>= 1) {
        if (tid < s) red[tid] += red[tid + s];
        __syncthreads();
    }
    float inv = 1.f / red[0];
    for (int i = tid; i < n; i += 256) row[i] *= inv;
}

__global__ void pool_v_kernel(const float* __restrict__ V,
                              const float* __restrict__ a,
                              float* __restrict__ v1)
{
    const int b = blockIdx.y;
    const int warp = threadIdx.x >> 5;
    const int lane = threadIdx.x & 31;
    const int d = blockIdx.x * 8 + warp;
    const float4* vr = reinterpret_cast<const float4*>(V + ((long)b * D_ + d) * M_);
    const float4* ar = reinterpret_cast<const float4*>(a + (long)b * M_);
    float acc = 0.f;
#pragma unroll
    for (int i = 0; i < M_ / 128; i++) {
        float4 v = vr[i * 32 + lane];
        float4 w = ar[i * 32 + lane];
        acc += v.x * w.x + v.y * w.y + v.z * w.z + v.w * w.w;
    }
#pragma unroll
    for (int o = 16; o > 0; o >>= 1) acc += __shfl_down_sync(0xffffffffu, acc, o);
    if (lane == 0) v1[b * D_ + d] = acc;
}

__global__ void pool_q_kernel(const float* __restrict__ Q,
                              const float* __restrict__ a,
                              float* __restrict__ q1)
{
    const int b = blockIdx.x;
    __shared__ float as[L_];
    for (int i = threadIdx.x; i < L_; i += blockDim.x) as[i] = a[b * L_ + i];
    __syncthreads();
    const int d = threadIdx.x;
    const float* qb = Q + (long)b * L_ * D_;
    float acc = 0.f;
#pragma unroll 8
    for (int l = 0; l < L_; l++) acc += as[l] * qb[(long)l * D_ + d];
    q1[b * D_ + d] = acc;
}

__global__ void bcast_kernel(float4* __restrict__ out,
                             const float4* __restrict__ src,
                             int rows)
{
    const long total4 = (long)B_ * rows * (D_ / 4);
    long i = (long)blockIdx.x * blockDim.x + threadIdx.x;
    if (i >= total4) return;
    int d4 = (int)(i % (D_ / 4));
    long br = i / (D_ / 4);
    int b = (int)(br / rows);
    out[i] = __ldg(&src[(long)b * (D_ / 4) + d4]);
}

// ===================== launch =================================================
extern "C" void kernel_launch(void* const* d_in, const int* in_sizes, int n_in,
                              void* d_out, int out_size)
{
    const float* V   = (const float*)d_in[0];  // [B, D, M]
    const float* Q   = (const float*)d_in[1];  // [B, L, D]
    const float* W_b = (const float*)d_in[2];  // [D, D]
    const float* W_v = (const float*)d_in[3];  // [K, D]
    const float* W_q = (const float*)d_in[4];  // [K, D]
    const float* whv = (const float*)d_in[5];  // [K]
    const float* whq = (const float*)d_in[6];  // [K]
    float* out = (float*)d_out;

    bf16 *pVt_h, *pVt_l, *pVn_h, *pVn_l, *pQn_h, *pQn_l, *pQt_h, *pQt_l;
    bf16 *pWbn_h, *pWbn_l, *pWbt_h, *pWbt_l;
    bf16 *pWv_h, *pWv_l, *pWq_h, *pWq_l;
    bf16 *pWqQ_h, *pWqQ_l, *pP_h, *pP_l, *pYv_h, *pYv_l;
    bf16 *pWvV_h, *pWvV_l, *pYq_h, *pYq_l, *pR_h, *pR_l;
    float *pWqQ_f, *p_zv, *p_zq, *p_v1, *p_q1;
    cudaGetSymbolAddress((void**)&pVt_h, g_Vt_hi);  cudaGetSymbolAddress((void**)&pVt_l, g_Vt_lo);
    cudaGetSymbolAddress((void**)&pVn_h, g_Vn_hi);  cudaGetSymbolAddress((void**)&pVn_l, g_Vn_lo);
    cudaGetSymbolAddress((void**)&pQn_h, g_Qn_hi);  cudaGetSymbolAddress((void**)&pQn_l, g_Qn_lo);
    cudaGetSymbolAddress((void**)&pQt_h, g_Qt_hi);  cudaGetSymbolAddress((void**)&pQt_l, g_Qt_lo);
    cudaGetSymbolAddress((void**)&pWbn_h, g_Wbn_hi); cudaGetSymbolAddress((void**)&pWbn_l, g_Wbn_lo);
    cudaGetSymbolAddress((void**)&pWbt_h, g_Wbt_hi); cudaGetSymbolAddress((void**)&pWbt_l, g_Wbt_lo);
    cudaGetSymbolAddress((void**)&pWv_h, g_Wv_hi);  cudaGetSymbolAddress((void**)&pWv_l, g_Wv_lo);
    cudaGetSymbolAddress((void**)&pWq_h, g_Wq_hi);  cudaGetSymbolAddress((void**)&pWq_l, g_Wq_lo);
    cudaGetSymbolAddress((void**)&pWqQ_h, g_WqQ_hi); cudaGetSymbolAddress((void**)&pWqQ_l, g_WqQ_lo);
    cudaGetSymbolAddress((void**)&pWqQ_f, g_WqQ_f);
    cudaGetSymbolAddress((void**)&pP_h, g_P_hi);    cudaGetSymbolAddress((void**)&pP_l, g_P_lo);
    cudaGetSymbolAddress((void**)&pYv_h, g_Yv_hi);  cudaGetSymbolAddress((void**)&pYv_l, g_Yv_lo);
    cudaGetSymbolAddress((void**)&pWvV_h, g_WvV_hi); cudaGetSymbolAddress((void**)&pWvV_l, g_WvV_lo);
    cudaGetSymbolAddress((void**)&pYq_h, g_Yq_hi);  cudaGetSymbolAddress((void**)&pYq_l, g_Yq_lo);
    cudaGetSymbolAddress((void**)&pR_h, g_R_hi);    cudaGetSymbolAddress((void**)&pR_l, g_R_lo);
    cudaGetSymbolAddress((void**)&p_zv, g_zv);      cudaGetSymbolAddress((void**)&p_zq, g_zq);
    cudaGetSymbolAddress((void**)&p_v1, g_v1);      cudaGetSymbolAddress((void**)&p_q1, g_q1);

    const int SM1 = 40960 + 1 * 4 * 2560 + 128;  // 51328 (NB=1)
    const int SM2 = 40960 + 2 * 4 * 2560 + 128;  // 61568 (NB=2)
    cudaFuncSetAttribute(tc_gemm<1, 0>, cudaFuncAttributeMaxDynamicSharedMemorySize, SM1);
    cudaFuncSetAttribute(tc_gemm<1, 1>, cudaFuncAttributeMaxDynamicSharedMemorySize, SM1);
    cudaFuncSetAttribute(tc_gemm<1, 3>, cudaFuncAttributeMaxDynamicSharedMemorySize, SM1);
    cudaFuncSetAttribute(tc_gemm<2, 2>, cudaFuncAttributeMaxDynamicSharedMemorySize, SM2);

    // ---- conversions
    conv_trans<<<dim3(M_ / 32, D_ / 32, B_), dim3(32, 8)>>>(
        V, pVn_h, pVn_l, pVt_h, pVt_l, D_, M_, (long)D_ * M_);
    conv_trans<<<dim3(D_ / 32, L_ / 32, B_), dim3(32, 8)>>>(
        Q, pQn_h, pQn_l, pQt_h, pQt_l, L_, D_, (long)L_ * D_);
    conv_trans<<<dim3(D_ / 32, D_ / 32, 1), dim3(32, 8)>>>(
        W_b, pWbn_h, pWbn_l, pWbt_h, pWbt_l, D_, D_, 0);
    conv_pad<<<(32 * D_) / 256, 256>>>(W_v, pWv_h, pWv_l, W_q, pWq_h, pWq_l);

    GJob j;
    // K1: WqQ[k,l] : A=Qn[L,D], B=Wq_s -> hi/lo + fp32
    j = { pQn_h, pQn_l, pWq_h, pWq_l, nullptr, nullptr,
          pWqQ_h, pWqQ_l, pWqQ_f, nullptr, nullptr,
          L_, D_, (long)L_ * D_, 0, 0 };
    tc_gemm<1, 1><<<dim3(L_ / 128, B_), 256, SM1>>>(j);

    // K2: P[k,e] : A=Qt[D,L], B=WqQ_s
    j = { pQt_h, pQt_l, pWqQ_h, pWqQ_l, nullptr, nullptr,
          pP_h, pP_l, nullptr, nullptr, nullptr,
          D_, L_, (long)D_ * L_, (long)32 * L_, 0 };
    tc_gemm<1, 0><<<dim3(D_ / 128, B_), 256, SM1>>>(j);

    // K3: Yv[k,e] : A=Wbt[D,D] (no batch), B=P_s
    j = { pWbt_h, pWbt_l, pP_h, pP_l, nullptr, nullptr,
          pYv_h, pYv_l, nullptr, nullptr, nullptr,
          D_, D_, 0, (long)32 * D_, 0 };
    tc_gemm<1, 0><<<dim3(D_ / 128, B_), 256, SM1>>>(j);

    // K4+K5+logits_v: A=Vt[M,D]; B0=Wv_s -> WvV ; B1=Yv_s -> Tv (fused logits)
    j = { pVt_h, pVt_l, pWv_h, pWv_l, pYv_h, pYv_l,
          pWvV_h, pWvV_l, nullptr, whv, p_zv,
          M_, D_, (long)M_ * D_, 0, (long)32 * D_ };
    tc_gemm<2, 2><<<dim3(M_ / 128, B_), 256, SM2>>>(j);

    // K6: Yq[k,e] : A=Vn[D,M], B=WvV_s
    j = { pVn_h, pVn_l, pWvV_h, pWvV_l, nullptr, nullptr,
          pYq_h, pYq_l, nullptr, nullptr, nullptr,
          D_, M_, (long)D_ * M_, (long)32 * M_, 0 };
    tc_gemm<1, 0><<<dim3(D_ / 128, B_), 256, SM1>>>(j);

    // K7: R[k,d] : A=Wbn[D,D] (no batch), B=Yq_s
    j = { pWbn_h, pWbn_l, pYq_h, pYq_l, nullptr, nullptr,
          pR_h, pR_l, nullptr, nullptr, nullptr,
          D_, D_, 0, (long)32 * D_, 0 };
    tc_gemm<1, 0><<<dim3(D_ / 128, B_), 256, SM1>>>(j);

    // K8+logits_q: A=Qn[L,D], B=R_s ; X = WqQ_f
    j = { pQn_h, pQn_l, pR_h, pR_l, nullptr, nullptr,
          nullptr, nullptr, pWqQ_f, whq, p_zq,
          L_, D_, (long)L_ * D_, (long)32 * D_, 0 };
    tc_gemm<1, 3><<<dim3(L_ / 128, B_), 256, SM1>>>(j);

    // softmax
    softmax_kernel<<<B_, 256>>>(p_zv, M_);
    softmax_kernel<<<B_, 256>>>(p_zq, L_);

    // pooled vectors
    {
        dim3 grid(D_ / 8, B_);
        pool_v_kernel<<<grid, 256>>>(V, p_zv, p_v1);
    }
    pool_q_kernel<<<B_, 512>>>(Q, p_zq, p_q1);

    // broadcast outputs: v [B,M,D] then q [B,L,D]
    {
        long n4v = (long)B_ * M_ * (D_ / 4);
        bcast_kernel<<<(unsigned)((n4v + 255) / 256), 256>>>(
            (float4*)out, (const float4*)p_v1, M_);
        long n4q = (long)B_ * L_ * (D_ / 4);
        float* out_q = out + (long)B_ * M_ * D_;
        bcast_kernel<<<(unsigned)((n4q + 255) / 256), 256>>>(
            (float4*)out_q, (const float4*)p_q1, L_);
    }
}

// round 7
// speedup vs baseline: 4.6578x; 1.1439x over previous
#include <cuda_runtime.h>
#include <cuda_bf16.h>
#include <math.h>
#include <stdint.h>

// Problem dims (fixed)
#define B_ 64
#define D_ 512
#define M_ 1024
#define L_ 256
#define KK_ 30

typedef __nv_bfloat16 bf16;

// ===================== device scratch =========================================
__device__ bf16 g_Wv_hi[32 * D_];
__device__ bf16 g_Wv_lo[32 * D_];
__device__ bf16 g_Wq_hi[32 * D_];
__device__ bf16 g_Wq_lo[32 * D_];
__device__ bf16 g_WqQ_hi[(long)B_ * 32 * L_];
__device__ bf16 g_WqQ_lo[(long)B_ * 32 * L_];
__device__ float g_WqQ_f[(long)B_ * 32 * L_];
__device__ bf16 g_P_hi[(long)B_ * 32 * D_];
__device__ bf16 g_P_lo[(long)B_ * 32 * D_];
__device__ bf16 g_Yv_hi[(long)B_ * 32 * D_];
__device__ bf16 g_Yv_lo[(long)B_ * 32 * D_];
__device__ bf16 g_WvV_hi[(long)B_ * 32 * M_];
__device__ bf16 g_WvV_lo[(long)B_ * 32 * M_];
__device__ bf16 g_Yq_hi[(long)B_ * 32 * D_];
__device__ bf16 g_Yq_lo[(long)B_ * 32 * D_];
__device__ bf16 g_R_hi[(long)B_ * 32 * D_];
__device__ bf16 g_R_lo[(long)B_ * 32 * D_];
__device__ float g_zv[B_ * M_];
__device__ float g_zq[B_ * L_];
__device__ float g_v1[B_ * D_];
__device__ float g_q1[B_ * D_];

// ===================== helpers ================================================
__device__ __forceinline__ uint32_t s2u(const void* p) {
    return (uint32_t)__cvta_generic_to_shared(p);
}
__device__ __forceinline__ void cp16(uint32_t dst, const void* src) {
    asm volatile("cp.async.cg.shared.global [%0], [%1], 16;" :: "r"(dst), "l"(src));
}
__device__ __forceinline__ void cp_commit() { asm volatile("cp.async.commit_group;"); }
__device__ __forceinline__ void cp_wait0()  { asm volatile("cp.async.wait_group 0;"); }

__device__ __forceinline__ void ldsm4(uint32_t* r, uint32_t addr) {
    asm volatile("ldmatrix.sync.aligned.m8n8.x4.shared.b16 {%0,%1,%2,%3}, [%4];"
                 : "=r"(r[0]), "=r"(r[1]), "=r"(r[2]), "=r"(r[3]) : "r"(addr));
}
__device__ __forceinline__ void ldsm4t(uint32_t* r, uint32_t addr) {
    asm volatile("ldmatrix.sync.aligned.m8n8.x4.trans.shared.b16 {%0,%1,%2,%3}, [%4];"
                 : "=r"(r[0]), "=r"(r[1]), "=r"(r[2]), "=r"(r[3]) : "r"(addr));
}
__device__ __forceinline__ void mma_bf(float* d, const uint32_t* a, const uint32_t* b) {
    asm volatile(
        "mma.sync.aligned.m16n8k16.row.col.f32.bf16.bf16.f32 "
        "{%0,%1,%2,%3}, {%4,%5,%6,%7}, {%8,%9}, {%0,%1,%2,%3};"
        : "+f"(d[0]), "+f"(d[1]), "+f"(d[2]), "+f"(d[3])
        : "r"(a[0]), "r"(a[1]), "r"(a[2]), "r"(a[3]), "r"(b[0]), "r"(b[1]));
}

__device__ __forceinline__ void split_bf(float x, bf16& h, bf16& l) {
    h = __float2bfloat16(x);
    l = __float2bfloat16(x - __bfloat162float(h));
}

// smem layout constants (bytes)
#define A_BUF 10240u     // slot size; AN uses 128x40 bf16 (10240B), TRA uses 32x272B (8704B)
#define B_BUF 2560u      // 32 x 40 bf16
#define BS_OFF 40960u    // after 4 A slots
#define CST 132          // Cs n-stride (floats), conflict-free epilogue

// ===================== weight pad conversion ==================================
__global__ void conv_pad(const float* __restrict__ Wv, bf16* __restrict__ Vh, bf16* __restrict__ Vl,
                         const float* __restrict__ Wq, bf16* __restrict__ Qh, bf16* __restrict__ Ql)
{
    int idx = blockIdx.x * blockDim.x + threadIdx.x;
    if (idx >= 32 * D_) return;
    int k = idx / D_, d = idx % D_;
    float a = (k < KK_) ? Wv[k * D_ + d] : 0.f;
    float b = (k < KK_) ? Wq[k * D_ + d] : 0.f;
    bf16 h, l;
    split_bf(a, h, l); Vh[idx] = h; Vl[idx] = l;
    split_bf(b, h, l); Qh[idx] = h; Ql[idx] = l;
}

// ===================== HMMA GEMM with on-the-fly fp32->bf16 hi/lo =============
// Ct[128-row m-tile of Nbig][32] = A(fp32) x S[32,Kd]^T (bf16 hi/lo, 3-term split)
// TRA=false: A natural [Nbig][Kd], row stride lda.
// TRA=true : A stored [Kd][Nbig] (row stride lda); fragments via ldmatrix.trans.
struct GJob {
    const float* A;                      // fp32 big operand
    int lda;                             // A row stride (elements)
    long sA;                             // A batch stride (elements)
    const bf16 *B0h, *B0l, *B1h, *B1l;   // small operands [32][Kd] bf16
    bf16 *Ch, *Cl;                       // out [b][32][Nbig]
    float* Cf;                           // EPI1: fp32 out; EPI3: fp32 X in
    const float* w;                      // logits weights (EPI 2/3)
    float* z;                            // logits out [b][Nbig] (EPI 2/3)
    int Nbig, Kd;
    long sB0, sB1;
};

// EPI: 0 = hi/lo out; 1 = hi/lo + fp32 out; 2 = (NB=2) hi/lo of acc0 + logits(acc0+acc1);
//      3 = logits(acc0 + fp32 X)
template<int NB, int EPI, bool TRA>
__global__ void __launch_bounds__(256) tc_gemm(GJob j)
{
    extern __shared__ char smem[];
    const uint32_t sb = s2u(smem);
    float* smw = (float*)(smem + BS_OFF + NB * 4 * B_BUF);

    const int tid = threadIdx.x;
    const int w = tid >> 5, lane = tid & 31;
    const int b = blockIdx.y;
    const int m0 = blockIdx.x * 128;

    const float* Ab = j.A + (long)b * j.sA;
    const bf16* Bb[2][2];
    Bb[0][0] = j.B0h + (long)b * j.sB0;
    Bb[0][1] = j.B0l + (long)b * j.sB0;
    if (NB == 2) {
        Bb[1][0] = j.B1h + (long)b * j.sB1;
        Bb[1][1] = j.B1l + (long)b * j.sB1;
    }

    if (EPI >= 2 && tid < KK_) smw[tid] = j.w[tid];

    // A gmem addressing (16 floats per thread per 32-k tile)
    const float* aptr = TRA
        ? (Ab + (long)(tid >> 3) * j.lda + m0 + (tid & 7) * 16)
        : (Ab + (long)(m0 + (tid >> 1)) * j.lda + (tid & 1) * 16);

    // A STS destination offset within a buffer slot (bytes)
    const uint32_t aSts = TRA ? (uint32_t)((tid >> 3) * 272 + (tid & 7) * 32)
                              : (uint32_t)((tid >> 1) * 80 + (tid & 1) * 32);

    // B staging indices
    const int bhl = tid >> 7, bi = tid & 127;
    const int br = bi >> 2, bc = bi & 3;

    const int T = j.Kd / 32;
    float4 fr[4];

    auto loadA = [&](int t) {
        const float* p = TRA ? (aptr + (long)t * 32 * j.lda) : (aptr + t * 32);
        fr[0] = *(const float4*)p;
        fr[1] = *(const float4*)(p + 4);
        fr[2] = *(const float4*)(p + 8);
        fr[3] = *(const float4*)(p + 12);
    };
    auto stsA = [&](int s) {
        uint32_t hp[8], lp[8];
        const float* f = (const float*)fr;
#pragma unroll
        for (int i = 0; i < 8; i++) {
            bf16 h0, l0, h1, l1;
            split_bf(f[2 * i], h0, l0);
            split_bf(f[2 * i + 1], h1, l1);
            hp[i] = (uint32_t)*(uint16_t*)&h0 | ((uint32_t)*(uint16_t*)&h1 << 16);
            lp[i] = (uint32_t)*(uint16_t*)&l0 | ((uint32_t)*(uint16_t*)&l1 << 16);
        }
        char* d0 = smem + (s * 2 + 0) * A_BUF + aSts;
        char* d1 = smem + (s * 2 + 1) * A_BUF + aSts;
        *(uint4*)d0        = make_uint4(hp[0], hp[1], hp[2], hp[3]);
        *(uint4*)(d0 + 16) = make_uint4(hp[4], hp[5], hp[6], hp[7]);
        *(uint4*)d1        = make_uint4(lp[0], lp[1], lp[2], lp[3]);
        *(uint4*)(d1 + 16) = make_uint4(lp[4], lp[5], lp[6], lp[7]);
    };
    auto stageB = [&](int t) {
        const int s = t & 1;
#pragma unroll
        for (int nb = 0; nb < NB; nb++) {
            uint32_t dst = sb + BS_OFF + (uint32_t)(((s * NB + nb) * 2 + bhl) * B_BUF)
                         + br * 80 + bc * 16;
            cp16(dst, Bb[nb][bhl] + (long)br * j.Kd + t * 32 + bc * 8);
        }
        cp_commit();
    };

    // ldmatrix lane addressing
    const uint32_t aLane = TRA
        ? (uint32_t)((((lane & 7) + 8 * (lane >> 4)) * 272) + (w * 16 + ((lane >> 3) & 1) * 8) * 2)
        : (uint32_t)((w * 16 + (lane & 15)) * 80 + (lane >> 4) * 16);
    const uint32_t aKs = TRA ? 4352u : 32u;  // ks step: 16 k-rows*272B vs 16 bf16
    const uint32_t bLaneRow = (uint32_t)((((lane >> 4) & 1) * 8 + (lane & 7)) * 80
                                         + ((lane >> 3) & 1) * 16);

    float acc[NB][4][4];
#pragma unroll
    for (int nb = 0; nb < NB; nb++)
#pragma unroll
        for (int nt = 0; nt < 4; nt++)
#pragma unroll
            for (int r = 0; r < 4; r++) acc[nb][nt][r] = 0.f;

    stageB(0);
    loadA(0);

    for (int t = 0; t < T; t++) {
        const int s = t & 1;
        cp_wait0();
        __syncthreads();   // B(t) landed; all warps done with A slot s (from t-2)

        stsA(s);
        if (t + 1 < T) { stageB(t + 1); loadA(t + 1); }
        __syncthreads();   // A tiles visible

        const uint32_t aH = sb + (uint32_t)((s * 2 + 0) * A_BUF) + aLane;
        const uint32_t aL = aH + A_BUF;

#pragma unroll
        for (int ks = 0; ks < 2; ks++) {
            uint32_t ah[4], al[4];
            if (TRA) { ldsm4t(ah, aH + ks * aKs); ldsm4t(al, aL + ks * aKs); }
            else     { ldsm4 (ah, aH + ks * aKs); ldsm4 (al, aL + ks * aKs); }
#pragma unroll
            for (int nb = 0; nb < NB; nb++) {
#pragma unroll
                for (int p = 0; p < 2; p++) {
                    uint32_t bbase = sb + BS_OFF
                        + (uint32_t)(((s * NB + nb) * 2 + 0) * B_BUF)
                        + (uint32_t)(p * 16 * 80) + bLaneRow + ks * 32;
                    uint32_t bh[4], bl[4];
                    ldsm4(bh, bbase);
                    ldsm4(bl, bbase + B_BUF);
                    mma_bf(acc[nb][2 * p],     ah, &bh[0]);
                    mma_bf(acc[nb][2 * p],     ah, &bl[0]);
                    mma_bf(acc[nb][2 * p],     al, &bh[0]);
                    mma_bf(acc[nb][2 * p + 1], ah, &bh[2]);
                    mma_bf(acc[nb][2 * p + 1], ah, &bl[2]);
                    mma_bf(acc[nb][2 * p + 1], al, &bh[2]);
                }
            }
        }
    }

    // ---------------- epilogue: stage accs in smem (reuses A region) ---------
    __syncthreads();
    float* Cs = (float*)smem;
    {
        const int g = lane >> 2, cc = lane & 3;
        const int m_l = w * 16 + g;
#pragma unroll
        for (int nb = 0; nb < NB; nb++) {
            float* C_ = Cs + nb * 32 * CST;
#pragma unroll
            for (int nt = 0; nt < 4; nt++) {
                int n0 = nt * 8 + cc * 2;
                C_[(n0 + 0) * CST + m_l]     = acc[nb][nt][0];
                C_[(n0 + 1) * CST + m_l]     = acc[nb][nt][1];
                C_[(n0 + 0) * CST + m_l + 8] = acc[nb][nt][2];
                C_[(n0 + 1) * CST + m_l + 8] = acc[nb][nt][3];
            }
        }
    }
    __syncthreads();

    if (EPI != 3) {
#pragma unroll
        for (int it = 0; it < 4; it++) {
            int q = tid + it * 256;
            int n = q >> 5, m4 = (q & 31) * 4;
            float4 v = *(float4*)&Cs[n * CST + m4];
            bf16 h0, l0, h1, l1, h2, l2, h3, l3;
            split_bf(v.x, h0, l0); split_bf(v.y, h1, l1);
            split_bf(v.z, h2, l2); split_bf(v.w, h3, l3);
            long o = ((long)b * 32 + n) * j.Nbig + m0 + m4;
            *(uint2*)(j.Ch + o) = make_uint2(
                ((uint32_t)*(uint16_t*)&h0) | ((uint32_t)*(uint16_t*)&h1 << 16),
                ((uint32_t)*(uint16_t*)&h2) | ((uint32_t)*(uint16_t*)&h3 << 16));
            *(uint2*)(j.Cl + o) = make_uint2(
                ((uint32_t)*(uint16_t*)&l0) | ((uint32_t)*(uint16_t*)&l1 << 16),
                ((uint32_t)*(uint16_t*)&l2) | ((uint32_t)*(uint16_t*)&l3 << 16));
            if (EPI == 1) *(float4*)(j.Cf + o) = v;
        }
    }
    if (EPI == 2) {
        if (tid < 128) {
            float zacc = 0.f;
#pragma unroll
            for (int k = 0; k < KK_; k++)
                zacc += smw[k] * tanhf(Cs[k * CST + tid] + Cs[(32 + k) * CST + tid]);
            j.z[(long)b * j.Nbig + m0 + tid] = zacc;
        }
    }
    if (EPI == 3) {
        if (tid < 128) {
            const float* X = j.Cf + (long)b * 32 * j.Nbig + m0 + tid;
            float zacc = 0.f;
#pragma unroll
            for (int k = 0; k < KK_; k++)
                zacc += smw[k] * tanhf(Cs[k * CST + tid] + X[(long)k * j.Nbig]);
            j.z[(long)b * j.Nbig + m0 + tid] = zacc;
        }
    }
}

// ===================== tail kernels ===========================================
__global__ void softmax_kernel(float* __restrict__ z, int n)
{
    const int b = blockIdx.x;
    float* row = z + (long)b * n;
    __shared__ float red[256];
    const int tid = threadIdx.x;

    float mx = -1e30f;
    for (int i = tid; i < n; i += 256) mx = fmaxf(mx, row[i]);
    red[tid] = mx; __syncthreads();
    for (int s = 128; s > 0; s >>= 1) {
        if (tid < s) red[tid] = fmaxf(red[tid], red[tid + s]);
        __syncthreads();
    }
    mx = red[0]; __syncthreads();

    float sum = 0.f;
    for (int i = tid; i < n; i += 256) {
        float e = expf(row[i] - mx);
        row[i] = e;
        sum += e;
    }
    red[tid] = sum; __syncthreads();
    for (int s = 128; s > 0; s >>= 1) {
        if (tid < s) red[tid] += red[tid + s];
        __syncthreads();
    }
    float inv = 1.f / red[0];
    for (int i = tid; i < n; i += 256) row[i] *= inv;
}

__global__ void pool_v_kernel(const float* __restrict__ V,
                              const float* __restrict__ a,
                              float* __restrict__ v1)
{
    const int b = blockIdx.y;
    const int warp = threadIdx.x >> 5;
    const int lane = threadIdx.x & 31;
    const int d = blockIdx.x * 8 + warp;
    const float4* vr = reinterpret_cast<const float4*>(V + ((long)b * D_ + d) * M_);
    const float4* ar = reinterpret_cast<const float4*>(a + (long)b * M_);
    float acc = 0.f;
#pragma unroll
    for (int i = 0; i < M_ / 128; i++) {
        float4 v = vr[i * 32 + lane];
        float4 w = ar[i * 32 + lane];
        acc += v.x * w.x + v.y * w.y + v.z * w.z + v.w * w.w;
    }
#pragma unroll
    for (int o = 16; o > 0; o >>= 1) acc += __shfl_down_sync(0xffffffffu, acc, o);
    if (lane == 0) v1[b * D_ + d] = acc;
}

__global__ void pool_q_kernel(const float* __restrict__ Q,
                              const float* __restrict__ a,
                              float* __restrict__ q1)
{
    const int b = blockIdx.x;
    __shared__ float as[L_];
    for (int i = threadIdx.x; i < L_; i += blockDim.x) as[i] = a[b * L_ + i];
    __syncthreads();
    const int d = threadIdx.x;
    const float* qb = Q + (long)b * L_ * D_;
    float acc = 0.f;
#pragma unroll 8
    for (int l = 0; l < L_; l++) acc += as[l] * qb[(long)l * D_ + d];
    q1[b * D_ + d] = acc;
}

__global__ void bcast_kernel(float4* __restrict__ out,
                             const float4* __restrict__ src,
                             int rows)
{
    const long total4 = (long)B_ * rows * (D_ / 4);
    long i = (long)blockIdx.x * blockDim.x + threadIdx.x;
    if (i >= total4) return;
    int d4 = (int)(i % (D_ / 4));
    long br = i / (D_ / 4);
    int b = (int)(br / rows);
    out[i] = __ldg(&src[(long)b * (D_ / 4) + d4]);
}

// ===================== launch =================================================
extern "C" void kernel_launch(void* const* d_in, const int* in_sizes, int n_in,
                              void* d_out, int out_size)
{
    const float* V   = (const float*)d_in[0];  // [B, D, M]
    const float* Q   = (const float*)d_in[1];  // [B, L, D]
    const float* W_b = (const float*)d_in[2];  // [D, D]
    const float* W_v = (const float*)d_in[3];  // [K, D]
    const float* W_q = (const float*)d_in[4];  // [K, D]
    const float* whv = (const float*)d_in[5];  // [K]
    const float* whq = (const float*)d_in[6];  // [K]
    float* out = (float*)d_out;

    bf16 *pWv_h, *pWv_l, *pWq_h, *pWq_l;
    bf16 *pWqQ_h, *pWqQ_l, *pP_h, *pP_l, *pYv_h, *pYv_l;
    bf16 *pWvV_h, *pWvV_l, *pYq_h, *pYq_l, *pR_h, *pR_l;
    float *pWqQ_f, *p_zv, *p_zq, *p_v1, *p_q1;
    cudaGetSymbolAddress((void**)&pWv_h, g_Wv_hi);  cudaGetSymbolAddress((void**)&pWv_l, g_Wv_lo);
    cudaGetSymbolAddress((void**)&pWq_h, g_Wq_hi);  cudaGetSymbolAddress((void**)&pWq_l, g_Wq_lo);
    cudaGetSymbolAddress((void**)&pWqQ_h, g_WqQ_hi); cudaGetSymbolAddress((void**)&pWqQ_l, g_WqQ_lo);
    cudaGetSymbolAddress((void**)&pWqQ_f, g_WqQ_f);
    cudaGetSymbolAddress((void**)&pP_h, g_P_hi);    cudaGetSymbolAddress((void**)&pP_l, g_P_lo);
    cudaGetSymbolAddress((void**)&pYv_h, g_Yv_hi);  cudaGetSymbolAddress((void**)&pYv_l, g_Yv_lo);
    cudaGetSymbolAddress((void**)&pWvV_h, g_WvV_hi); cudaGetSymbolAddress((void**)&pWvV_l, g_WvV_lo);
    cudaGetSymbolAddress((void**)&pYq_h, g_Yq_hi);  cudaGetSymbolAddress((void**)&pYq_l, g_Yq_lo);
    cudaGetSymbolAddress((void**)&pR_h, g_R_hi);    cudaGetSymbolAddress((void**)&pR_l, g_R_lo);
    cudaGetSymbolAddress((void**)&p_zv, g_zv);      cudaGetSymbolAddress((void**)&p_zq, g_zq);
    cudaGetSymbolAddress((void**)&p_v1, g_v1);      cudaGetSymbolAddress((void**)&p_q1, g_q1);

    const int SM1 = (int)(BS_OFF + 1 * 4 * B_BUF + 128);  // 51328
    const int SM2 = (int)(BS_OFF + 2 * 4 * B_BUF + 128);  // 61568
    cudaFuncSetAttribute(tc_gemm<1, 1, false>, cudaFuncAttributeMaxDynamicSharedMemorySize, SM1);
    cudaFuncSetAttribute(tc_gemm<1, 0, true>,  cudaFuncAttributeMaxDynamicSharedMemorySize, SM1);
    cudaFuncSetAttribute(tc_gemm<2, 2, true>,  cudaFuncAttributeMaxDynamicSharedMemorySize, SM2);
    cudaFuncSetAttribute(tc_gemm<1, 0, false>, cudaFuncAttributeMaxDynamicSharedMemorySize, SM1);
    cudaFuncSetAttribute(tc_gemm<1, 3, false>, cudaFuncAttributeMaxDynamicSharedMemorySize, SM1);

    // weight pad conversion (only precompute left)
    conv_pad<<<(32 * D_ + 255) / 256, 256>>>(W_v, pWv_h, pWv_l, W_q, pWq_h, pWq_l);

    GJob j;
    // K1: WqQ[k,l] = sum_d Wq[k,d] Q[l,d] : A=Q natural [L][D] (AN), hi/lo + fp32 out
    j = { Q, D_, (long)L_ * D_, pWq_h, pWq_l, nullptr, nullptr,
          pWqQ_h, pWqQ_l, pWqQ_f, nullptr, nullptr, L_, D_, 0, 0 };
    tc_gemm<1, 1, false><<<dim3(L_ / 128, B_), 256, SM1>>>(j);

    // K2: P[k,e] = sum_l WqQ[k,l] Q[l,e] : A=Q^T via TRA (S=Q [l][e], lda=D)
    j = { Q, D_, (long)L_ * D_, pWqQ_h, pWqQ_l, nullptr, nullptr,
          pP_h, pP_l, nullptr, nullptr, nullptr, D_, L_, (long)32 * L_, 0 };
    tc_gemm<1, 0, true><<<dim3(D_ / 128, B_), 256, SM1>>>(j);

    // K3: Yv[k,e] = sum_d P[k,d] Wb[d,e] : A=Wb^T via TRA (S=Wb [d][e], no batch)
    j = { W_b, D_, 0, pP_h, pP_l, nullptr, nullptr,
          pYv_h, pYv_l, nullptr, nullptr, nullptr, D_, D_, (long)32 * D_, 0 };
    tc_gemm<1, 0, true><<<dim3(D_ / 128, B_), 256, SM1>>>(j);

    // K4+K5+logits_v: A=V^T via TRA (S=V [d][m], lda=M); B0=Wv -> WvV; B1=Yv -> Tv
    j = { V, M_, (long)D_ * M_, pWv_h, pWv_l, pYv_h, pYv_l,
          pWvV_h, pWvV_l, nullptr, whv, p_zv, M_, D_, 0, (long)32 * D_ };
    tc_gemm<2, 2, true><<<dim3(M_ / 128, B_), 256, SM2>>>(j);

    // K6: Yq[k,e] = sum_m WvV[k,m] V[e,m] : A=V natural [D][M] (AN)
    j = { V, M_, (long)D_ * M_, pWvV_h, pWvV_l, nullptr, nullptr,
          pYq_h, pYq_l, nullptr, nullptr, nullptr, D_, M_, (long)32 * M_, 0 };
    tc_gemm<1, 0, false><<<dim3(D_ / 128, B_), 256, SM1>>>(j);

    // K7: R[k,d] = sum_e Yq[k,e] Wb[d,e] : A=Wb natural (AN, no batch)
    j = { W_b, D_, 0, pYq_h, pYq_l, nullptr, nullptr,
          pR_h, pR_l, nullptr, nullptr, nullptr, D_, D_, (long)32 * D_, 0 };
    tc_gemm<1, 0, false><<<dim3(D_ / 128, B_), 256, SM1>>>(j);

    // K8+logits_q: Tq[k,l] = sum_d R[k,d] Q[l,d] : A=Q natural (AN); X=WqQ_f
    j = { Q, D_, (long)L_ * D_, pR_h, pR_l, nullptr, nullptr,
          nullptr, nullptr, pWqQ_f, whq, p_zq, L_, D_, (long)32 * D_, 0 };
    tc_gemm<1, 3, false><<<dim3(L_ / 128, B_), 256, SM1>>>(j);

    // softmax
    softmax_kernel<<<B_, 256>>>(p_zv, M_);
    softmax_kernel<<<B_, 256>>>(p_zq, L_);

    // pooled vectors
    {
        dim3 grid(D_ / 8, B_);
        pool_v_kernel<<<grid, 256>>>(V, p_zv, p_v1);
    }
    pool_q_kernel<<<B_, 512>>>(Q, p_zq, p_q1);

    // broadcast outputs: v [B,M,D] then q [B,L,D]
    {
        long n4v = (long)B_ * M_ * (D_ / 4);
        bcast_kernel<<<(unsigned)((n4v + 255) / 256), 256>>>(
            (float4*)out, (const float4*)p_v1, M_);
        long n4q = (long)B_ * L_ * (D_ / 4);
        float* out_q = out + (long)B_ * M_ * D_;
        bcast_kernel<<<(unsigned)((n4q + 255) / 256), 256>>>(
            (float4*)out_q, (const float4*)p_q1, L_);
    }
}